// round 1
// baseline (speedup 1.0000x reference)
#include <cuda_runtime.h>
#include <math.h>

// ---------------- problem constants ----------------
#define EMB  1024
#define NH   16
#define HD   64
#define FF   4096
#define TSEQ 1024
#define BT   4096          // B * T rows

// ---------------- scratch (no allocations allowed) ----------------
__device__ float g_h  [BT * EMB];            // LN output (reused twice)
__device__ float g_qkv[BT * 3 * EMB];        // QKV projections
__device__ float g_ctx[BT * EMB];            // attention context
__device__ float g_x2 [BT * EMB];            // residual after attention
__device__ float g_ff [BT * FF];             // FC1 output

// ---------------- LayerNorm: one block per row ----------------
__global__ __launch_bounds__(256)
void ln_kernel(const float* __restrict__ x, const float* __restrict__ w,
               const float* __restrict__ b, float* __restrict__ out)
{
    int row = blockIdx.x;
    int tid = threadIdx.x;
    const float* xr = x + (size_t)row * EMB;
    float4 v = *(const float4*)(xr + tid * 4);
    float s  = v.x + v.y + v.z + v.w;
    float sq = v.x * v.x + v.y * v.y + v.z * v.z + v.w * v.w;
    #pragma unroll
    for (int o = 16; o > 0; o >>= 1) {
        s  += __shfl_xor_sync(0xffffffffu, s,  o);
        sq += __shfl_xor_sync(0xffffffffu, sq, o);
    }
    __shared__ float rs[8], rq[8];
    int wid = tid >> 5, lane = tid & 31;
    if (lane == 0) { rs[wid] = s; rq[wid] = sq; }
    __syncthreads();
    if (tid == 0) {
        float S = 0.f, Q = 0.f;
        #pragma unroll
        for (int i = 0; i < 8; i++) { S += rs[i]; Q += rq[i]; }
        rs[0] = S; rq[0] = Q;
    }
    __syncthreads();
    float mean = rs[0] * (1.f / EMB);
    float var  = rq[0] * (1.f / EMB) - mean * mean;
    float inv  = rsqrtf(var + 1e-5f);
    float4 wv = *(const float4*)(w + tid * 4);
    float4 bv = *(const float4*)(b + tid * 4);
    float4 o;
    o.x = (v.x - mean) * inv * wv.x + bv.x;
    o.y = (v.y - mean) * inv * wv.y + bv.y;
    o.z = (v.z - mean) * inv * wv.z + bv.z;
    o.w = (v.w - mean) * inv * wv.w + bv.w;
    *(float4*)(out + (size_t)row * EMB + tid * 4) = o;
}

// ---------------- fp32 SGEMM (NT): C[M,N] = A[M,K] @ W[N,K]^T + bias (+epi) ----
// EPI: 0 = bias, 1 = bias + exact GELU, 2 = bias + residual
__device__ __forceinline__ float gelu_f(float v)
{
    return 0.5f * v * (1.0f + erff(v * 0.70710678118654752f));
}

template<int EPI>
__global__ __launch_bounds__(256)
void sgemm_nt(const float* __restrict__ A, const float* __restrict__ W,
              const float* __restrict__ bias, const float* __restrict__ res,
              float* __restrict__ C, int M, int N, int K)
{
    __shared__ float As[2][8][128];
    __shared__ float Ws[2][8][128];
    const int tid = threadIdx.x;
    const int bm = blockIdx.y, bn = blockIdx.x;
    const int tx = tid & 15, ty = tid >> 4;
    const int lr = tid >> 1;
    const int lc = (tid & 1) * 4;

    const float* Ag = A + (size_t)(bm * 128 + lr) * K + lc;
    const float* Wg = W + (size_t)(bn * 128 + lr) * K + lc;

    {
        float4 ra = *(const float4*)Ag;
        float4 rw = *(const float4*)Wg;
        As[0][lc + 0][lr] = ra.x; As[0][lc + 1][lr] = ra.y;
        As[0][lc + 2][lr] = ra.z; As[0][lc + 3][lr] = ra.w;
        Ws[0][lc + 0][lr] = rw.x; Ws[0][lc + 1][lr] = rw.y;
        Ws[0][lc + 2][lr] = rw.z; Ws[0][lc + 3][lr] = rw.w;
    }
    __syncthreads();

    float acc[8][8];
    #pragma unroll
    for (int i = 0; i < 8; i++)
        #pragma unroll
        for (int j = 0; j < 8; j++) acc[i][j] = 0.f;

    const int nk = K >> 3;
    int buf = 0;
    for (int kt = 1; kt < nk; ++kt) {
        float4 na = *(const float4*)(Ag + kt * 8);
        float4 nw = *(const float4*)(Wg + kt * 8);
        #pragma unroll
        for (int kk = 0; kk < 8; kk++) {
            float4 a0 = *(const float4*)(&As[buf][kk][ty * 8]);
            float4 a1 = *(const float4*)(&As[buf][kk][ty * 8 + 4]);
            float4 b0 = *(const float4*)(&Ws[buf][kk][tx * 8]);
            float4 b1 = *(const float4*)(&Ws[buf][kk][tx * 8 + 4]);
            float av[8] = {a0.x, a0.y, a0.z, a0.w, a1.x, a1.y, a1.z, a1.w};
            float bv[8] = {b0.x, b0.y, b0.z, b0.w, b1.x, b1.y, b1.z, b1.w};
            #pragma unroll
            for (int i = 0; i < 8; i++)
                #pragma unroll
                for (int j = 0; j < 8; j++)
                    acc[i][j] += av[i] * bv[j];
        }
        buf ^= 1;
        As[buf][lc + 0][lr] = na.x; As[buf][lc + 1][lr] = na.y;
        As[buf][lc + 2][lr] = na.z; As[buf][lc + 3][lr] = na.w;
        Ws[buf][lc + 0][lr] = nw.x; Ws[buf][lc + 1][lr] = nw.y;
        Ws[buf][lc + 2][lr] = nw.z; Ws[buf][lc + 3][lr] = nw.w;
        __syncthreads();
    }
    #pragma unroll
    for (int kk = 0; kk < 8; kk++) {
        float4 a0 = *(const float4*)(&As[buf][kk][ty * 8]);
        float4 a1 = *(const float4*)(&As[buf][kk][ty * 8 + 4]);
        float4 b0 = *(const float4*)(&Ws[buf][kk][tx * 8]);
        float4 b1 = *(const float4*)(&Ws[buf][kk][tx * 8 + 4]);
        float av[8] = {a0.x, a0.y, a0.z, a0.w, a1.x, a1.y, a1.z, a1.w};
        float bv[8] = {b0.x, b0.y, b0.z, b0.w, b1.x, b1.y, b1.z, b1.w};
        #pragma unroll
        for (int i = 0; i < 8; i++)
            #pragma unroll
            for (int j = 0; j < 8; j++)
                acc[i][j] += av[i] * bv[j];
    }

    // epilogue
    const int row0 = bm * 128 + ty * 8;
    const int col0 = bn * 128 + tx * 8;
    float bias8[8];
    #pragma unroll
    for (int j = 0; j < 8; j++) bias8[j] = bias[col0 + j];
    #pragma unroll
    for (int i = 0; i < 8; i++) {
        float v[8];
        #pragma unroll
        for (int j = 0; j < 8; j++) {
            float t = acc[i][j] + bias8[j];
            if (EPI == 1) t = gelu_f(t);
            v[j] = t;
        }
        size_t off = (size_t)(row0 + i) * N + col0;
        if (EPI == 2) {
            float4 r0 = *(const float4*)(res + off);
            float4 r1 = *(const float4*)(res + off + 4);
            v[0] += r0.x; v[1] += r0.y; v[2] += r0.z; v[3] += r0.w;
            v[4] += r1.x; v[5] += r1.y; v[6] += r1.z; v[7] += r1.w;
        }
        float4 o0 = {v[0], v[1], v[2], v[3]};
        float4 o1 = {v[4], v[5], v[6], v[7]};
        *(float4*)(C + off)     = o0;
        *(float4*)(C + off + 4) = o1;
    }
}

// ---------------- flash attention (fp32, causal) ----------------
// grid: (B*NH, TSEQ/64), block 128.  Each thread: query row r = tid/2,
// owns 32 key-cols (QK stage) and 32 d-values (PV stage), half = tid&1.
__global__ __launch_bounds__(128)
void attn_kernel(const float* __restrict__ qkv, float* __restrict__ ctx)
{
    extern __shared__ float sm[];
    float (*Qs)[65]  = (float(*)[65])sm;                              // 64x65
    float (*Kst)[68] = (float(*)[68])(sm + 64 * 65);                  // [d][kc]
    float (*Vs)[64]  = (float(*)[64])(sm + 64 * 65 + 64 * 68);        // [kc][d]
    float (*Ps)[65]  = (float(*)[65])(sm + 64 * 65 + 64 * 68 + 64 * 64);

    const int b  = blockIdx.x >> 4;
    const int h  = blockIdx.x & 15;
    const int qt = blockIdx.y;
    const int tid = threadIdx.x;
    const int r   = tid >> 1;
    const int off = (tid & 1) * 32;
    const int q0  = qt * 64;
    const size_t rowstride = 3 * EMB;

    // load Q tile (pre-scaled by 1/sqrt(D))
    const float* qg = qkv + (size_t)(b * TSEQ + q0 + r) * rowstride + h * HD + off;
    #pragma unroll
    for (int i = 0; i < 32; i += 4) {
        float4 v = *(const float4*)(qg + i);
        Qs[r][off + i + 0] = v.x * 0.125f;
        Qs[r][off + i + 1] = v.y * 0.125f;
        Qs[r][off + i + 2] = v.z * 0.125f;
        Qs[r][off + i + 3] = v.w * 0.125f;
    }

    float m_run = -1e30f, l_run = 0.f;
    float O[32];
    #pragma unroll
    for (int i = 0; i < 32; i++) O[i] = 0.f;

    for (int j = 0; j <= qt; ++j) {
        const int k0 = j * 64;
        __syncthreads();                 // previous PV done + (j==0) Q visible
        {
            const int kc = tid >> 1;
            const float* kg = qkv + (size_t)(b * TSEQ + k0 + kc) * rowstride + EMB + h * HD + off;
            const float* vg = kg + EMB;
            #pragma unroll
            for (int i = 0; i < 32; i += 4) {
                float4 kv = *(const float4*)(kg + i);
                Kst[off + i + 0][kc] = kv.x;
                Kst[off + i + 1][kc] = kv.y;
                Kst[off + i + 2][kc] = kv.z;
                Kst[off + i + 3][kc] = kv.w;
                *(float4*)(&Vs[kc][off + i]) = *(const float4*)(vg + i);
            }
        }
        __syncthreads();

        // S = Q K^T for this thread's 32 key columns
        float s[32];
        #pragma unroll
        for (int c = 0; c < 32; c++) s[c] = 0.f;
        #pragma unroll 4
        for (int d = 0; d < 64; ++d) {
            float q = Qs[r][d];
            #pragma unroll
            for (int c = 0; c < 32; c += 4) {
                float4 kk = *(const float4*)(&Kst[d][off + c]);
                s[c + 0] += q * kk.x;
                s[c + 1] += q * kk.y;
                s[c + 2] += q * kk.z;
                s[c + 3] += q * kk.w;
            }
        }
        if (j == qt) {
            #pragma unroll
            for (int c = 0; c < 32; c++)
                if (k0 + off + c > q0 + r) s[c] = -1e30f;
        }

        // online softmax (pair = 2 threads per row)
        float mx = s[0];
        #pragma unroll
        for (int c = 1; c < 32; c++) mx = fmaxf(mx, s[c]);
        mx = fmaxf(mx, __shfl_xor_sync(0xffffffffu, mx, 1));
        float m_new = fmaxf(m_run, mx);
        float alpha = __expf(m_run - m_new);
        float lsum = 0.f;
        #pragma unroll
        for (int c = 0; c < 32; c++) {
            float p = __expf(s[c] - m_new);
            lsum += p;
            Ps[r][off + c] = p;
        }
        lsum += __shfl_xor_sync(0xffffffffu, lsum, 1);
        l_run = l_run * alpha + lsum;
        m_run = m_new;
        #pragma unroll
        for (int i = 0; i < 32; i++) O[i] *= alpha;
        __syncthreads();

        // O += P V   (this thread's 32 d-values, all 64 key rows)
        #pragma unroll 4
        for (int kc = 0; kc < 64; ++kc) {
            float p = Ps[r][kc];
            #pragma unroll
            for (int i = 0; i < 32; i += 4) {
                float4 vv = *(const float4*)(&Vs[kc][off + i]);
                O[i + 0] += p * vv.x;
                O[i + 1] += p * vv.y;
                O[i + 2] += p * vv.z;
                O[i + 3] += p * vv.w;
            }
        }
    }

    const float inv = 1.f / l_run;
    float* og = ctx + (size_t)(b * TSEQ + q0 + r) * EMB + h * HD + off;
    #pragma unroll
    for (int i = 0; i < 32; i += 4) {
        float4 o = {O[i] * inv, O[i + 1] * inv, O[i + 2] * inv, O[i + 3] * inv};
        *(float4*)(og + i) = o;
    }
}

// ---------------- launch ----------------
extern "C" void kernel_launch(void* const* d_in, const int* in_sizes, int n_in,
                              void* d_out, int out_size)
{
    const float* x    = (const float*)d_in[0];
    const float* ln1w = (const float*)d_in[1];
    const float* ln1b = (const float*)d_in[2];
    const float* ln2w = (const float*)d_in[3];
    const float* ln2b = (const float*)d_in[4];
    const float* qkvw = (const float*)d_in[5];
    const float* qkvb = (const float*)d_in[6];
    const float* outw = (const float*)d_in[7];
    const float* outb = (const float*)d_in[8];
    const float* fc1w = (const float*)d_in[9];
    const float* fc1b = (const float*)d_in[10];
    const float* fc2w = (const float*)d_in[11];
    const float* fc2b = (const float*)d_in[12];
    float* out = (float*)d_out;

    float *ph, *pqkv, *pctx, *px2, *pff;
    cudaGetSymbolAddress((void**)&ph,   g_h);
    cudaGetSymbolAddress((void**)&pqkv, g_qkv);
    cudaGetSymbolAddress((void**)&pctx, g_ctx);
    cudaGetSymbolAddress((void**)&px2,  g_x2);
    cudaGetSymbolAddress((void**)&pff,  g_ff);

    const int ATT_SMEM = (64 * 65 + 64 * 68 + 64 * 64 + 64 * 65) * 4;  // 67072 B
    cudaFuncSetAttribute(attn_kernel,
                         cudaFuncAttributeMaxDynamicSharedMemorySize, ATT_SMEM);

    // 1) LN1
    ln_kernel<<<BT, 256>>>(x, ln1w, ln1b, ph);
    // 2) QKV projection: [4096,1024] x [3072,1024]^T
    sgemm_nt<0><<<dim3(3 * EMB / 128, BT / 128), 256>>>(ph, qkvw, qkvb, nullptr,
                                                        pqkv, BT, 3 * EMB, EMB);
    // 3) causal flash attention
    attn_kernel<<<dim3(4 * NH, TSEQ / 64), 128, ATT_SMEM>>>(pqkv, pctx);
    // 4) out projection + residual(x)
    sgemm_nt<2><<<dim3(EMB / 128, BT / 128), 256>>>(pctx, outw, outb, x,
                                                    px2, BT, EMB, EMB);
    // 5) LN2
    ln_kernel<<<BT, 256>>>(px2, ln2w, ln2b, ph);
    // 6) FC1 + GELU
    sgemm_nt<1><<<dim3(FF / 128, BT / 128), 256>>>(ph, fc1w, fc1b, nullptr,
                                                   pff, BT, FF, EMB);
    // 7) FC2 + residual(x2) -> d_out
    sgemm_nt<2><<<dim3(EMB / 128, BT / 128), 256>>>(pff, fc2w, fc2b, px2,
                                                    out, BT, EMB, FF);
}

// round 12
// speedup vs baseline: 2.1677x; 2.1677x over previous
#include <cuda_runtime.h>
#include <cuda_bf16.h>
#include <math.h>
#include <cstdint>

typedef __nv_bfloat16 bf16;

// ---------------- problem constants ----------------
#define EMB  1024
#define NH   16
#define HD   64
#define FF   4096
#define TSEQ 1024
#define BT   4096          // B * T rows

// ---------------- GEMM tile config ----------------
#define BM 128
#define BN 128
#define BK 64              // 64 bf16 = 128 bytes per row (SW128 atom)
#define STAGES 3
#define STAGE_BYTES 65536  // Ahi 16K + Alo 16K + Bhi 16K + Blo 16K
#define GEMM_SMEM (STAGES * STAGE_BYTES)

// ---------------- scratch (no allocations allowed) ----------------
__device__ bf16  g_hhi [BT * EMB];
__device__ bf16  g_hlo [BT * EMB];
__device__ float g_qkv [BT * 3 * EMB];
__device__ bf16  g_ctxh[BT * EMB];
__device__ bf16  g_ctxl[BT * EMB];
__device__ float g_x2  [BT * EMB];
__device__ bf16  g_ffh [BT * FF];
__device__ bf16  g_ffl [BT * FF];
__device__ bf16  g_wqh [3 * EMB * EMB];
__device__ bf16  g_wql [3 * EMB * EMB];
__device__ bf16  g_woh [EMB * EMB];
__device__ bf16  g_wol [EMB * EMB];
__device__ bf16  g_w1h [FF * EMB];
__device__ bf16  g_w1l [FF * EMB];
__device__ bf16  g_w2h [EMB * FF];
__device__ bf16  g_w2l [EMB * FF];

// ---------------- helpers ----------------
__device__ __forceinline__ uint32_t smem_u32(const void* p) {
    uint32_t a;
    asm("{ .reg .u64 t; cvta.to.shared.u64 t, %1; cvt.u32.u64 %0, t; }"
        : "=r"(a) : "l"(p));
    return a;
}
#define SWZ128(o) ((o) ^ (((o) >> 3) & 0x70))

#define CP16(dst, src) \
    asm volatile("cp.async.cg.shared.global [%0], [%1], 16;" :: "r"(dst), "l"(src))
#define CP_COMMIT() asm volatile("cp.async.commit_group;" ::: "memory")
#define CP_WAIT1()  asm volatile("cp.async.wait_group 1;" ::: "memory")

#define LDSM4(r, addr)                                                         \
    asm volatile("ldmatrix.sync.aligned.m8n8.x4.shared.b16 {%0,%1,%2,%3}, [%4];" \
        : "=r"((r)[0]), "=r"((r)[1]), "=r"((r)[2]), "=r"((r)[3]) : "r"(addr))

__device__ __forceinline__ void split2(float v, bf16& h, bf16& l) {
    h = __float2bfloat16(v);
    l = __float2bfloat16(v - __bfloat162float(h));
}
__device__ __forceinline__ float gelu_f(float v) {
    return 0.5f * v * (1.0f + erff(v * 0.70710678118654752f));
}

// ---------------- weight split kernel ----------------
__global__ __launch_bounds__(256)
void split_kernel(const float* __restrict__ w, bf16* __restrict__ hi,
                  bf16* __restrict__ lo, int n4)
{
    int i = blockIdx.x * 256 + threadIdx.x;
    if (i >= n4) return;
    float4 v = *(const float4*)(w + i * 4);
    bf16 h[4], l[4];
    split2(v.x, h[0], l[0]); split2(v.y, h[1], l[1]);
    split2(v.z, h[2], l[2]); split2(v.w, h[3], l[3]);
    *(uint2*)(hi + i * 4) = *(uint2*)h;
    *(uint2*)(lo + i * 4) = *(uint2*)l;
}

// ---------------- LayerNorm (fp32 in, bf16 hi/lo out) ----------------
__global__ __launch_bounds__(256)
void ln_split_kernel(const float* __restrict__ x, const float* __restrict__ w,
                     const float* __restrict__ b, bf16* __restrict__ ohi,
                     bf16* __restrict__ olo)
{
    int row = blockIdx.x;
    int tid = threadIdx.x;
    const float* xr = x + (size_t)row * EMB;
    float4 v = *(const float4*)(xr + tid * 4);
    float s  = v.x + v.y + v.z + v.w;
    float sq = v.x * v.x + v.y * v.y + v.z * v.z + v.w * v.w;
    #pragma unroll
    for (int o = 16; o > 0; o >>= 1) {
        s  += __shfl_xor_sync(0xffffffffu, s,  o);
        sq += __shfl_xor_sync(0xffffffffu, sq, o);
    }
    __shared__ float rs[8], rq[8];
    int wid = tid >> 5, lane = tid & 31;
    if (lane == 0) { rs[wid] = s; rq[wid] = sq; }
    __syncthreads();
    if (tid == 0) {
        float S = 0.f, Q = 0.f;
        #pragma unroll
        for (int i = 0; i < 8; i++) { S += rs[i]; Q += rq[i]; }
        rs[0] = S; rq[0] = Q;
    }
    __syncthreads();
    float mean = rs[0] * (1.f / EMB);
    float var  = rq[0] * (1.f / EMB) - mean * mean;
    float inv  = rsqrtf(var + 1e-5f);
    float4 wv = *(const float4*)(w + tid * 4);
    float4 bv = *(const float4*)(b + tid * 4);
    float o0 = (v.x - mean) * inv * wv.x + bv.x;
    float o1 = (v.y - mean) * inv * wv.y + bv.y;
    float o2 = (v.z - mean) * inv * wv.z + bv.z;
    float o3 = (v.w - mean) * inv * wv.w + bv.w;
    bf16 h[4], l[4];
    split2(o0, h[0], l[0]); split2(o1, h[1], l[1]);
    split2(o2, h[2], l[2]); split2(o3, h[3], l[3]);
    size_t off = (size_t)row * EMB + tid * 4;
    *(uint2*)(ohi + off) = *(uint2*)h;
    *(uint2*)(olo + off) = *(uint2*)l;
}

// ---------------- mma.sync bf16-split GEMM ----------------
// C[M,N] = A[M,K] @ W[N,K]^T + bias, hi/lo split operands, fp32 accum regs.
// EPI 0: f32 out (bias) | EPI 1: bias+GELU -> bf16 hi/lo | EPI 2: bias+res -> f32
__device__ __forceinline__ void fill_stage(uint32_t stage,
    const bf16* __restrict__ Ahi, const bf16* __restrict__ Alo,
    const bf16* __restrict__ Whi, const bf16* __restrict__ Wlo,
    int K, int c, int bm, int bn, int tid)
{
    const size_t a0 = (size_t)(bm * BM) * K + (size_t)c * BK;
    const size_t b0 = (size_t)(bn * BN) * K + (size_t)c * BK;
    #pragma unroll
    for (int i = 0; i < 4; i++) {
        int idx = tid + i * 256;
        int r = idx >> 3, s = idx & 7;
        uint32_t so = SWZ128((uint32_t)(r * 128 + s * 16));
        size_t ga = a0 + (size_t)r * K + s * 8;
        size_t gb = b0 + (size_t)r * K + s * 8;
        CP16(stage + so,          Ahi + ga);
        CP16(stage + 16384 + so,  Alo + ga);
        CP16(stage + 32768 + so,  Whi + gb);
        CP16(stage + 49152 + so,  Wlo + gb);
    }
}

__device__ __forceinline__ void mma_pass(float (&acc)[4][4][4],
                                         uint32_t (&a)[4][4], uint32_t (&b)[2][4])
{
    #pragma unroll
    for (int i = 0; i < 4; i++)
        #pragma unroll
        for (int j8 = 0; j8 < 4; j8++) {
            uint32_t b0 = b[j8 >> 1][(j8 & 1) * 2];
            uint32_t b1 = b[j8 >> 1][(j8 & 1) * 2 + 1];
            asm volatile(
                "mma.sync.aligned.m16n8k16.row.col.f32.bf16.bf16.f32 "
                "{%0,%1,%2,%3}, {%4,%5,%6,%7}, {%8,%9}, {%0,%1,%2,%3};"
                : "+f"(acc[i][j8][0]), "+f"(acc[i][j8][1]),
                  "+f"(acc[i][j8][2]), "+f"(acc[i][j8][3])
                : "r"(a[i][0]), "r"(a[i][1]), "r"(a[i][2]), "r"(a[i][3]),
                  "r"(b0), "r"(b1));
        }
}

__device__ __forceinline__ void compute_chunk(uint32_t stage, int wm, int wn,
                                              int lane, float (&acc)[4][4][4])
{
    const uint32_t sa_hi = stage;
    const uint32_t sa_lo = stage + 16384;
    const uint32_t sb_hi = stage + 32768;
    const uint32_t sb_lo = stage + 49152;
    const int mrow = lane & 7, msel = lane >> 3;
    const int arow = wm * 64 + (msel & 1) * 8 + mrow;   // + i*16
    const int akb  = msel >> 1;
    const int brow = wn * 32 + (msel >> 1) * 8 + mrow;  // + j*16
    const int bkb  = msel & 1;

    #pragma unroll
    for (int ks = 0; ks < 4; ks++) {
        uint32_t ahi[4][4], alo[4][4], bhi[2][4], blo[2][4];
        #pragma unroll
        for (int i = 0; i < 4; i++) {
            uint32_t off = SWZ128((uint32_t)(((arow + i * 16) << 7) +
                                             ((ks * 2 + akb) << 4)));
            LDSM4(ahi[i], sa_hi + off);
        }
        #pragma unroll
        for (int j = 0; j < 2; j++) {
            uint32_t off = SWZ128((uint32_t)(((brow + j * 16) << 7) +
                                             ((ks * 2 + bkb) << 4)));
            LDSM4(bhi[j], sb_hi + off);
        }
        mma_pass(acc, ahi, bhi);               // hi * hi
        #pragma unroll
        for (int j = 0; j < 2; j++) {
            uint32_t off = SWZ128((uint32_t)(((brow + j * 16) << 7) +
                                             ((ks * 2 + bkb) << 4)));
            LDSM4(blo[j], sb_lo + off);
        }
        mma_pass(acc, ahi, blo);               // hi * lo
        #pragma unroll
        for (int i = 0; i < 4; i++) {
            uint32_t off = SWZ128((uint32_t)(((arow + i * 16) << 7) +
                                             ((ks * 2 + akb) << 4)));
            LDSM4(alo[i], sa_lo + off);
        }
        mma_pass(acc, alo, bhi);               // lo * hi
    }
}

template<int EPI>
__global__ __launch_bounds__(256, 1)
void mma_gemm(const bf16* __restrict__ Ahi, const bf16* __restrict__ Alo,
              const bf16* __restrict__ Whi, const bf16* __restrict__ Wlo,
              const float* __restrict__ bias, const float* __restrict__ res,
              float* __restrict__ Cf, bf16* __restrict__ Chi, bf16* __restrict__ Clo,
              int M, int N, int K)
{
    extern __shared__ char smraw[];
    const uint32_t sbase = smem_u32(smraw);
    const int tid = threadIdx.x;
    const int bm = blockIdx.y, bn = blockIdx.x;
    const int wid = tid >> 5, lane = tid & 31;
    const int wm = wid & 1, wn = wid >> 1;
    const int NC = K >> 6;

    float acc[4][4][4];
    #pragma unroll
    for (int i = 0; i < 4; i++)
        #pragma unroll
        for (int j = 0; j < 4; j++)
            #pragma unroll
            for (int k = 0; k < 4; k++) acc[i][j][k] = 0.f;

    fill_stage(sbase,               Ahi, Alo, Whi, Wlo, K, 0, bm, bn, tid);
    CP_COMMIT();
    fill_stage(sbase + STAGE_BYTES, Ahi, Alo, Whi, Wlo, K, 1, bm, bn, tid);
    CP_COMMIT();

    for (int c = 0; c < NC; ++c) {
        CP_WAIT1();
        __syncthreads();
        if (c + 2 < NC)
            fill_stage(sbase + ((c + 2) % STAGES) * STAGE_BYTES,
                       Ahi, Alo, Whi, Wlo, K, c + 2, bm, bn, tid);
        CP_COMMIT();
        compute_chunk(sbase + (c % STAGES) * STAGE_BYTES, wm, wn, lane, acc);
    }

    // ---- epilogue ----
    const int row0 = bm * BM + wm * 64 + (lane >> 2);
    const int colw = bn * BN + wn * 32 + (lane & 3) * 2;
    #pragma unroll
    for (int i = 0; i < 4; i++) {
        #pragma unroll
        for (int j8 = 0; j8 < 4; j8++) {
            const int col = colw + j8 * 8;
            float2 bb = *(const float2*)(bias + col);
            float v0 = acc[i][j8][0] + bb.x;
            float v1 = acc[i][j8][1] + bb.y;
            float v2 = acc[i][j8][2] + bb.x;
            float v3 = acc[i][j8][3] + bb.y;
            const size_t o0 = (size_t)(row0 + i * 16) * N + col;
            const size_t o1 = o0 + (size_t)8 * N;
            if (EPI == 1) {
                bf16 h[2], l[2];
                split2(gelu_f(v0), h[0], l[0]);
                split2(gelu_f(v1), h[1], l[1]);
                *(uint32_t*)(Chi + o0) = *(uint32_t*)h;
                *(uint32_t*)(Clo + o0) = *(uint32_t*)l;
                split2(gelu_f(v2), h[0], l[0]);
                split2(gelu_f(v3), h[1], l[1]);
                *(uint32_t*)(Chi + o1) = *(uint32_t*)h;
                *(uint32_t*)(Clo + o1) = *(uint32_t*)l;
            } else {
                if (EPI == 2) {
                    float2 r0v = *(const float2*)(res + o0);
                    float2 r1v = *(const float2*)(res + o1);
                    v0 += r0v.x; v1 += r0v.y; v2 += r1v.x; v3 += r1v.y;
                }
                float2 w0 = {v0, v1}, w1 = {v2, v3};
                *(float2*)(Cf + o0) = w0;
                *(float2*)(Cf + o1) = w1;
            }
        }
    }
}

// ---------------- flash attention (fp32, causal), split bf16 output ----------------
__global__ __launch_bounds__(128)
void attn_kernel(const float* __restrict__ qkv, bf16* __restrict__ ctxh,
                 bf16* __restrict__ ctxl)
{
    extern __shared__ float sm[];
    float (*Qs)[65]  = (float(*)[65])sm;
    float (*Kst)[68] = (float(*)[68])(sm + 64 * 65);
    float (*Vs)[64]  = (float(*)[64])(sm + 64 * 65 + 64 * 68);
    float (*Ps)[65]  = (float(*)[65])(sm + 64 * 65 + 64 * 68 + 64 * 64);

    const int b  = blockIdx.x >> 4;
    const int h  = blockIdx.x & 15;
    const int qt = blockIdx.y;
    const int tid = threadIdx.x;
    const int r   = tid >> 1;
    const int off = (tid & 1) * 32;
    const int q0  = qt * 64;
    const size_t rowstride = 3 * EMB;

    const float* qg = qkv + (size_t)(b * TSEQ + q0 + r) * rowstride + h * HD + off;
    #pragma unroll
    for (int i = 0; i < 32; i += 4) {
        float4 v = *(const float4*)(qg + i);
        Qs[r][off + i + 0] = v.x * 0.125f;
        Qs[r][off + i + 1] = v.y * 0.125f;
        Qs[r][off + i + 2] = v.z * 0.125f;
        Qs[r][off + i + 3] = v.w * 0.125f;
    }

    float m_run = -1e30f, l_run = 0.f;
    float O[32];
    #pragma unroll
    for (int i = 0; i < 32; i++) O[i] = 0.f;

    for (int j = 0; j <= qt; ++j) {
        const int k0 = j * 64;
        __syncthreads();
        {
            const int kc = tid >> 1;
            const float* kg = qkv + (size_t)(b * TSEQ + k0 + kc) * rowstride + EMB + h * HD + off;
            const float* vg = kg + EMB;
            #pragma unroll
            for (int i = 0; i < 32; i += 4) {
                float4 kv = *(const float4*)(kg + i);
                Kst[off + i + 0][kc] = kv.x;
                Kst[off + i + 1][kc] = kv.y;
                Kst[off + i + 2][kc] = kv.z;
                Kst[off + i + 3][kc] = kv.w;
                *(float4*)(&Vs[kc][off + i]) = *(const float4*)(vg + i);
            }
        }
        __syncthreads();

        float s[32];
        #pragma unroll
        for (int c = 0; c < 32; c++) s[c] = 0.f;
        #pragma unroll 4
        for (int d = 0; d < 64; ++d) {
            float q = Qs[r][d];
            #pragma unroll
            for (int c = 0; c < 32; c += 4) {
                float4 kk = *(const float4*)(&Kst[d][off + c]);
                s[c + 0] += q * kk.x;
                s[c + 1] += q * kk.y;
                s[c + 2] += q * kk.z;
                s[c + 3] += q * kk.w;
            }
        }
        if (j == qt) {
            #pragma unroll
            for (int c = 0; c < 32; c++)
                if (k0 + off + c > q0 + r) s[c] = -1e30f;
        }

        float mx = s[0];
        #pragma unroll
        for (int c = 1; c < 32; c++) mx = fmaxf(mx, s[c]);
        mx = fmaxf(mx, __shfl_xor_sync(0xffffffffu, mx, 1));
        float m_new = fmaxf(m_run, mx);
        float alpha = __expf(m_run - m_new);
        float lsum = 0.f;
        #pragma unroll
        for (int c = 0; c < 32; c++) {
            float p = __expf(s[c] - m_new);
            lsum += p;
            Ps[r][off + c] = p;
        }
        lsum += __shfl_xor_sync(0xffffffffu, lsum, 1);
        l_run = l_run * alpha + lsum;
        m_run = m_new;
        #pragma unroll
        for (int i = 0; i < 32; i++) O[i] *= alpha;
        __syncthreads();

        #pragma unroll 4
        for (int kc = 0; kc < 64; ++kc) {
            float p = Ps[r][kc];
            #pragma unroll
            for (int i = 0; i < 32; i += 4) {
                float4 vv = *(const float4*)(&Vs[kc][off + i]);
                O[i + 0] += p * vv.x;
                O[i + 1] += p * vv.y;
                O[i + 2] += p * vv.z;
                O[i + 3] += p * vv.w;
            }
        }
    }

    const float inv = 1.f / l_run;
    const size_t ob = (size_t)(b * TSEQ + q0 + r) * EMB + h * HD + off;
    #pragma unroll
    for (int i = 0; i < 32; i += 4) {
        bf16 hb[4], lb[4];
        split2(O[i + 0] * inv, hb[0], lb[0]);
        split2(O[i + 1] * inv, hb[1], lb[1]);
        split2(O[i + 2] * inv, hb[2], lb[2]);
        split2(O[i + 3] * inv, hb[3], lb[3]);
        *(uint2*)(ctxh + ob + i) = *(uint2*)hb;
        *(uint2*)(ctxl + ob + i) = *(uint2*)lb;
    }
}

// ---------------- launch ----------------
extern "C" void kernel_launch(void* const* d_in, const int* in_sizes, int n_in,
                              void* d_out, int out_size)
{
    const float* x    = (const float*)d_in[0];
    const float* ln1w = (const float*)d_in[1];
    const float* ln1b = (const float*)d_in[2];
    const float* ln2w = (const float*)d_in[3];
    const float* ln2b = (const float*)d_in[4];
    const float* qkvw = (const float*)d_in[5];
    const float* qkvb = (const float*)d_in[6];
    const float* outw = (const float*)d_in[7];
    const float* outb = (const float*)d_in[8];
    const float* fc1w = (const float*)d_in[9];
    const float* fc1b = (const float*)d_in[10];
    const float* fc2w = (const float*)d_in[11];
    const float* fc2b = (const float*)d_in[12];
    float* out = (float*)d_out;

    bf16 *hhi, *hlo, *ctxh, *ctxl, *ffh, *ffl;
    bf16 *wqh, *wql, *woh, *wol, *w1h, *w1l, *w2h, *w2l;
    float *pqkv, *px2;
    cudaGetSymbolAddress((void**)&hhi,  g_hhi);
    cudaGetSymbolAddress((void**)&hlo,  g_hlo);
    cudaGetSymbolAddress((void**)&pqkv, g_qkv);
    cudaGetSymbolAddress((void**)&ctxh, g_ctxh);
    cudaGetSymbolAddress((void**)&ctxl, g_ctxl);
    cudaGetSymbolAddress((void**)&px2,  g_x2);
    cudaGetSymbolAddress((void**)&ffh,  g_ffh);
    cudaGetSymbolAddress((void**)&ffl,  g_ffl);
    cudaGetSymbolAddress((void**)&wqh,  g_wqh);
    cudaGetSymbolAddress((void**)&wql,  g_wql);
    cudaGetSymbolAddress((void**)&woh,  g_woh);
    cudaGetSymbolAddress((void**)&wol,  g_wol);
    cudaGetSymbolAddress((void**)&w1h,  g_w1h);
    cudaGetSymbolAddress((void**)&w1l,  g_w1l);
    cudaGetSymbolAddress((void**)&w2h,  g_w2h);
    cudaGetSymbolAddress((void**)&w2l,  g_w2l);

    cudaFuncSetAttribute(mma_gemm<0>, cudaFuncAttributeMaxDynamicSharedMemorySize, GEMM_SMEM);
    cudaFuncSetAttribute(mma_gemm<1>, cudaFuncAttributeMaxDynamicSharedMemorySize, GEMM_SMEM);
    cudaFuncSetAttribute(mma_gemm<2>, cudaFuncAttributeMaxDynamicSharedMemorySize, GEMM_SMEM);
    const int ATT_SMEM = (64 * 65 + 64 * 68 + 64 * 64 + 64 * 65) * 4;
    cudaFuncSetAttribute(attn_kernel,
                         cudaFuncAttributeMaxDynamicSharedMemorySize, ATT_SMEM);

    // 0) split weights into bf16 hi/lo
    split_kernel<<<3 * EMB * EMB / 4 / 256, 256>>>(qkvw, wqh, wql, 3 * EMB * EMB / 4);
    split_kernel<<<EMB * EMB / 4 / 256, 256>>>(outw, woh, wol, EMB * EMB / 4);
    split_kernel<<<FF * EMB / 4 / 256, 256>>>(fc1w, w1h, w1l, FF * EMB / 4);
    split_kernel<<<EMB * FF / 4 / 256, 256>>>(fc2w, w2h, w2l, EMB * FF / 4);

    // 1) LN1 (split output)
    ln_split_kernel<<<BT, 256>>>(x, ln1w, ln1b, hhi, hlo);
    // 2) QKV projection
    mma_gemm<0><<<dim3(3 * EMB / BN, BT / BM), 256, GEMM_SMEM>>>(
        hhi, hlo, wqh, wql, qkvb, nullptr, pqkv, nullptr, nullptr, BT, 3 * EMB, EMB);
    // 3) causal flash attention (split output)
    attn_kernel<<<dim3(4 * NH, TSEQ / 64), 128, ATT_SMEM>>>(pqkv, ctxh, ctxl);
    // 4) out projection + residual(x)
    mma_gemm<2><<<dim3(EMB / BN, BT / BM), 256, GEMM_SMEM>>>(
        ctxh, ctxl, woh, wol, outb, x, px2, nullptr, nullptr, BT, EMB, EMB);
    // 5) LN2 (split output)
    ln_split_kernel<<<BT, 256>>>(px2, ln2w, ln2b, hhi, hlo);
    // 6) FC1 + GELU (split output)
    mma_gemm<1><<<dim3(FF / BN, BT / BM), 256, GEMM_SMEM>>>(
        hhi, hlo, w1h, w1l, fc1b, nullptr, nullptr, ffh, ffl, BT, FF, EMB);
    // 7) FC2 + residual(x2) -> d_out
    mma_gemm<2><<<dim3(EMB / BN, BT / BM), 256, GEMM_SMEM>>>(
        ffh, ffl, w2h, w2l, fc2b, px2, out, nullptr, nullptr, BT, EMB, FF);
}

// round 14
// speedup vs baseline: 2.1921x; 1.0113x over previous
#include <cuda_runtime.h>
#include <cuda_bf16.h>
#include <math.h>
#include <cstdint>

// ---------------- problem constants ----------------
#define EMB  1024
#define NH   16
#define HD   64
#define FF   4096
#define TSEQ 1024
#define BT   4096          // B * T rows

// ---------------- GEMM tile config (tf32) ----------------
#define BM 128
#define BN 128
#define BK 32              // 32 tf32 = 128 bytes per row (SW128 atom)
#define STAGES 3
#define STAGE_BYTES 32768  // A 16K + B 16K
#define GEMM_SMEM (STAGES * STAGE_BYTES)

// ---------------- scratch (no allocations allowed) ----------------
__device__ float g_h  [BT * EMB];        // LN output, tf32-rounded
__device__ float g_qkv[BT * 3 * EMB];    // QKV (fp32, attn input)
__device__ float g_ctx[BT * EMB];        // attention out, tf32-rounded
__device__ float g_x2 [BT * EMB];        // residual after attention (fp32)
__device__ float g_ff [BT * FF];         // FC1+GELU out, tf32-rounded
__device__ float g_wq [3 * EMB * EMB];   // tf32-rounded weights
__device__ float g_wo [EMB * EMB];
__device__ float g_w1 [FF * EMB];
__device__ float g_w2 [EMB * FF];

// ---------------- helpers ----------------
__device__ __forceinline__ uint32_t smem_u32(const void* p) {
    uint32_t a;
    asm("{ .reg .u64 t; cvta.to.shared.u64 t, %1; cvt.u32.u64 %0, t; }"
        : "=r"(a) : "l"(p));
    return a;
}
#define SWZ128(o) ((o) ^ (((o) >> 3) & 0x70))

#define CP16(dst, src) \
    asm volatile("cp.async.cg.shared.global [%0], [%1], 16;" :: "r"(dst), "l"(src))
#define CP_COMMIT() asm volatile("cp.async.commit_group;" ::: "memory")
#define CP_WAIT1()  asm volatile("cp.async.wait_group 1;" ::: "memory")

__device__ __forceinline__ uint32_t lds32(uint32_t addr) {
    uint32_t v;
    asm volatile("ld.shared.b32 %0, [%1];" : "=r"(v) : "r"(addr));
    return v;
}
__device__ __forceinline__ float to_tf32(float v) {
    uint32_t o;
    asm("cvt.rna.tf32.f32 %0, %1;" : "=r"(o) : "f"(v));
    return __uint_as_float(o);
}
__device__ __forceinline__ float gelu_f(float v) {
    return 0.5f * v * (1.0f + erff(v * 0.70710678118654752f));
}

// ---------------- weight tf32-round kernel ----------------
__global__ __launch_bounds__(256)
void round_kernel(const float* __restrict__ w, float* __restrict__ o, int n4)
{
    int i = blockIdx.x * 256 + threadIdx.x;
    if (i >= n4) return;
    float4 v = *(const float4*)(w + i * 4);
    float4 r;
    r.x = to_tf32(v.x); r.y = to_tf32(v.y);
    r.z = to_tf32(v.z); r.w = to_tf32(v.w);
    *(float4*)(o + i * 4) = r;
}

// ---------------- LayerNorm (fp32 in, tf32-rounded fp32 out) ----------------
__global__ __launch_bounds__(256)
void ln_kernel(const float* __restrict__ x, const float* __restrict__ w,
               const float* __restrict__ b, float* __restrict__ out)
{
    int row = blockIdx.x;
    int tid = threadIdx.x;
    const float* xr = x + (size_t)row * EMB;
    float4 v = *(const float4*)(xr + tid * 4);
    float s  = v.x + v.y + v.z + v.w;
    float sq = v.x * v.x + v.y * v.y + v.z * v.z + v.w * v.w;
    #pragma unroll
    for (int o = 16; o > 0; o >>= 1) {
        s  += __shfl_xor_sync(0xffffffffu, s,  o);
        sq += __shfl_xor_sync(0xffffffffu, sq, o);
    }
    __shared__ float rs[8], rq[8];
    int wid = tid >> 5, lane = tid & 31;
    if (lane == 0) { rs[wid] = s; rq[wid] = sq; }
    __syncthreads();
    if (tid == 0) {
        float S = 0.f, Q = 0.f;
        #pragma unroll
        for (int i = 0; i < 8; i++) { S += rs[i]; Q += rq[i]; }
        rs[0] = S; rq[0] = Q;
    }
    __syncthreads();
    float mean = rs[0] * (1.f / EMB);
    float var  = rq[0] * (1.f / EMB) - mean * mean;
    float inv  = rsqrtf(var + 1e-5f);
    float4 wv = *(const float4*)(w + tid * 4);
    float4 bv = *(const float4*)(b + tid * 4);
    float4 o;
    o.x = to_tf32((v.x - mean) * inv * wv.x + bv.x);
    o.y = to_tf32((v.y - mean) * inv * wv.y + bv.y);
    o.z = to_tf32((v.z - mean) * inv * wv.z + bv.z);
    o.w = to_tf32((v.w - mean) * inv * wv.w + bv.w);
    *(float4*)(out + (size_t)row * EMB + tid * 4) = o;
}

// ---------------- tf32 mma.sync GEMM ----------------
// C[M,N] = A[M,K] @ W[N,K]^T + bias; A,W pre-rounded to tf32.
// EPI 0: fp32 out (bias) | EPI 1: bias+GELU -> tf32-rounded | EPI 2: bias+res fp32
__device__ __forceinline__ void fill_stage(uint32_t stage,
    const float* __restrict__ A, const float* __restrict__ W,
    int K, int c, int bm, int bn, int tid)
{
    const size_t a0 = (size_t)(bm * BM) * K + (size_t)c * BK;
    const size_t b0 = (size_t)(bn * BN) * K + (size_t)c * BK;
    #pragma unroll
    for (int i = 0; i < 4; i++) {
        int idx = tid + i * 256;
        int r = idx >> 3, s = idx & 7;
        uint32_t so = SWZ128((uint32_t)(r * 128 + s * 16));
        CP16(stage + so,          A + a0 + (size_t)r * K + s * 4);
        CP16(stage + 16384 + so,  W + b0 + (size_t)r * K + s * 4);
    }
}

__device__ __forceinline__ void compute_chunk(uint32_t stage, int wm, int wn,
                                              int lane, float (&acc)[4][4][4])
{
    const uint32_t sa = stage;
    const uint32_t sb = stage + 16384;
    const int grp = lane >> 2, qid = lane & 3;
    const int arow0 = wm * 64 + grp;   // + i*16 (+8)
    const int brow0 = wn * 32 + grp;   // + j*8

    #pragma unroll
    for (int k8 = 0; k8 < 4; k8++) {
        const int c0 = k8 * 8 + qid;       // tf32 column
        uint32_t a[4][4], b[4][2];
        #pragma unroll
        for (int i = 0; i < 4; i++) {
            int r0 = arow0 + i * 16, r1 = r0 + 8;
            a[i][0] = lds32(sa + SWZ128((uint32_t)(r0 * 128 + c0 * 4)));
            a[i][1] = lds32(sa + SWZ128((uint32_t)(r1 * 128 + c0 * 4)));
            a[i][2] = lds32(sa + SWZ128((uint32_t)(r0 * 128 + (c0 + 4) * 4)));
            a[i][3] = lds32(sa + SWZ128((uint32_t)(r1 * 128 + (c0 + 4) * 4)));
        }
        #pragma unroll
        for (int j = 0; j < 4; j++) {
            int rn = brow0 + j * 8;
            b[j][0] = lds32(sb + SWZ128((uint32_t)(rn * 128 + c0 * 4)));
            b[j][1] = lds32(sb + SWZ128((uint32_t)(rn * 128 + (c0 + 4) * 4)));
        }
        #pragma unroll
        for (int i = 0; i < 4; i++)
            #pragma unroll
            for (int j = 0; j < 4; j++) {
                asm volatile(
                    "mma.sync.aligned.m16n8k8.row.col.f32.tf32.tf32.f32 "
                    "{%0,%1,%2,%3}, {%4,%5,%6,%7}, {%8,%9}, {%0,%1,%2,%3};"
                    : "+f"(acc[i][j][0]), "+f"(acc[i][j][1]),
                      "+f"(acc[i][j][2]), "+f"(acc[i][j][3])
                    : "r"(a[i][0]), "r"(a[i][1]), "r"(a[i][2]), "r"(a[i][3]),
                      "r"(b[j][0]), "r"(b[j][1]));
            }
    }
}

template<int EPI>
__global__ __launch_bounds__(256)
void tf32_gemm(const float* __restrict__ A, const float* __restrict__ W,
               const float* __restrict__ bias, const float* __restrict__ res,
               float* __restrict__ C, int M, int N, int K)
{
    extern __shared__ char smraw[];
    const uint32_t sbase = smem_u32(smraw);
    const int tid = threadIdx.x;
    const int bm = blockIdx.y, bn = blockIdx.x;
    const int wid = tid >> 5, lane = tid & 31;
    const int wm = wid & 1, wn = wid >> 1;
    const int NC = K >> 5;

    float acc[4][4][4];
    #pragma unroll
    for (int i = 0; i < 4; i++)
        #pragma unroll
        for (int j = 0; j < 4; j++)
            #pragma unroll
            for (int k = 0; k < 4; k++) acc[i][j][k] = 0.f;

    fill_stage(sbase,               A, W, K, 0, bm, bn, tid);
    CP_COMMIT();
    fill_stage(sbase + STAGE_BYTES, A, W, K, 1, bm, bn, tid);
    CP_COMMIT();

    for (int c = 0; c < NC; ++c) {
        CP_WAIT1();
        __syncthreads();
        if (c + 2 < NC)
            fill_stage(sbase + ((c + 2) % STAGES) * STAGE_BYTES,
                       A, W, K, c + 2, bm, bn, tid);
        CP_COMMIT();
        compute_chunk(sbase + (c % STAGES) * STAGE_BYTES, wm, wn, lane, acc);
    }

    // ---- epilogue (m16n8 C layout) ----
    const int row0 = bm * BM + wm * 64 + (lane >> 2);
    const int colw = bn * BN + wn * 32 + (lane & 3) * 2;
    #pragma unroll
    for (int i = 0; i < 4; i++) {
        #pragma unroll
        for (int j8 = 0; j8 < 4; j8++) {
            const int col = colw + j8 * 8;
            float2 bb = *(const float2*)(bias + col);
            float v0 = acc[i][j8][0] + bb.x;
            float v1 = acc[i][j8][1] + bb.y;
            float v2 = acc[i][j8][2] + bb.x;
            float v3 = acc[i][j8][3] + bb.y;
            const size_t o0 = (size_t)(row0 + i * 16) * N + col;
            const size_t o1 = o0 + (size_t)8 * N;
            if (EPI == 1) {
                float2 w0 = {to_tf32(gelu_f(v0)), to_tf32(gelu_f(v1))};
                float2 w1 = {to_tf32(gelu_f(v2)), to_tf32(gelu_f(v3))};
                *(float2*)(C + o0) = w0;
                *(float2*)(C + o1) = w1;
            } else {
                if (EPI == 2) {
                    float2 r0v = *(const float2*)(res + o0);
                    float2 r1v = *(const float2*)(res + o1);
                    v0 += r0v.x; v1 += r0v.y; v2 += r1v.x; v3 += r1v.y;
                }
                float2 w0 = {v0, v1}, w1 = {v2, v3};
                *(float2*)(C + o0) = w0;
                *(float2*)(C + o1) = w1;
            }
        }
    }
}

// ---------------- flash attention (fp32, causal), tf32-rounded output ----------
__global__ __launch_bounds__(128)
void attn_kernel(const float* __restrict__ qkv, float* __restrict__ ctx)
{
    extern __shared__ float sm[];
    float (*Qs)[65]  = (float(*)[65])sm;
    float (*Kst)[68] = (float(*)[68])(sm + 64 * 65);
    float (*Vs)[64]  = (float(*)[64])(sm + 64 * 65 + 64 * 68);
    float (*Ps)[65]  = (float(*)[65])(sm + 64 * 65 + 64 * 68 + 64 * 64);

    const int b  = blockIdx.x >> 4;
    const int h  = blockIdx.x & 15;
    const int qt = blockIdx.y;
    const int tid = threadIdx.x;
    const int r   = tid >> 1;
    const int off = (tid & 1) * 32;
    const int q0  = qt * 64;
    const size_t rowstride = 3 * EMB;

    const float* qg = qkv + (size_t)(b * TSEQ + q0 + r) * rowstride + h * HD + off;
    #pragma unroll
    for (int i = 0; i < 32; i += 4) {
        float4 v = *(const float4*)(qg + i);
        Qs[r][off + i + 0] = v.x * 0.125f;
        Qs[r][off + i + 1] = v.y * 0.125f;
        Qs[r][off + i + 2] = v.z * 0.125f;
        Qs[r][off + i + 3] = v.w * 0.125f;
    }

    float m_run = -1e30f, l_run = 0.f;
    float O[32];
    #pragma unroll
    for (int i = 0; i < 32; i++) O[i] = 0.f;

    for (int j = 0; j <= qt; ++j) {
        const int k0 = j * 64;
        __syncthreads();
        {
            const int kc = tid >> 1;
            const float* kg = qkv + (size_t)(b * TSEQ + k0 + kc) * rowstride + EMB + h * HD + off;
            const float* vg = kg + EMB;
            #pragma unroll
            for (int i = 0; i < 32; i += 4) {
                float4 kv = *(const float4*)(kg + i);
                Kst[off + i + 0][kc] = kv.x;
                Kst[off + i + 1][kc] = kv.y;
                Kst[off + i + 2][kc] = kv.z;
                Kst[off + i + 3][kc] = kv.w;
                *(float4*)(&Vs[kc][off + i]) = *(const float4*)(vg + i);
            }
        }
        __syncthreads();

        float s[32];
        #pragma unroll
        for (int c = 0; c < 32; c++) s[c] = 0.f;
        #pragma unroll 4
        for (int d = 0; d < 64; ++d) {
            float q = Qs[r][d];
            #pragma unroll
            for (int c = 0; c < 32; c += 4) {
                float4 kk = *(const float4*)(&Kst[d][off + c]);
                s[c + 0] += q * kk.x;
                s[c + 1] += q * kk.y;
                s[c + 2] += q * kk.z;
                s[c + 3] += q * kk.w;
            }
        }
        if (j == qt) {
            #pragma unroll
            for (int c = 0; c < 32; c++)
                if (k0 + off + c > q0 + r) s[c] = -1e30f;
        }

        float mx = s[0];
        #pragma unroll
        for (int c = 1; c < 32; c++) mx = fmaxf(mx, s[c]);
        mx = fmaxf(mx, __shfl_xor_sync(0xffffffffu, mx, 1));
        float m_new = fmaxf(m_run, mx);
        float alpha = __expf(m_run - m_new);
        float lsum = 0.f;
        #pragma unroll
        for (int c = 0; c < 32; c++) {
            float p = __expf(s[c] - m_new);
            lsum += p;
            Ps[r][off + c] = p;
        }
        lsum += __shfl_xor_sync(0xffffffffu, lsum, 1);
        l_run = l_run * alpha + lsum;
        m_run = m_new;
        #pragma unroll
        for (int i = 0; i < 32; i++) O[i] *= alpha;
        __syncthreads();

        #pragma unroll 4
        for (int kc = 0; kc < 64; ++kc) {
            float p = Ps[r][kc];
            #pragma unroll
            for (int i = 0; i < 32; i += 4) {
                float4 vv = *(const float4*)(&Vs[kc][off + i]);
                O[i + 0] += p * vv.x;
                O[i + 1] += p * vv.y;
                O[i + 2] += p * vv.z;
                O[i + 3] += p * vv.w;
            }
        }
    }

    const float inv = 1.f / l_run;
    float* og = ctx + (size_t)(b * TSEQ + q0 + r) * EMB + h * HD + off;
    #pragma unroll
    for (int i = 0; i < 32; i += 4) {
        float4 o;
        o.x = to_tf32(O[i + 0] * inv);
        o.y = to_tf32(O[i + 1] * inv);
        o.z = to_tf32(O[i + 2] * inv);
        o.w = to_tf32(O[i + 3] * inv);
        *(float4*)(og + i) = o;
    }
}

// ---------------- launch ----------------
extern "C" void kernel_launch(void* const* d_in, const int* in_sizes, int n_in,
                              void* d_out, int out_size)
{
    const float* x    = (const float*)d_in[0];
    const float* ln1w = (const float*)d_in[1];
    const float* ln1b = (const float*)d_in[2];
    const float* ln2w = (const float*)d_in[3];
    const float* ln2b = (const float*)d_in[4];
    const float* qkvw = (const float*)d_in[5];
    const float* qkvb = (const float*)d_in[6];
    const float* outw = (const float*)d_in[7];
    const float* outb = (const float*)d_in[8];
    const float* fc1w = (const float*)d_in[9];
    const float* fc1b = (const float*)d_in[10];
    const float* fc2w = (const float*)d_in[11];
    const float* fc2b = (const float*)d_in[12];
    float* out = (float*)d_out;

    float *ph, *pqkv, *pctx, *px2, *pff, *pwq, *pwo, *pw1, *pw2;
    cudaGetSymbolAddress((void**)&ph,   g_h);
    cudaGetSymbolAddress((void**)&pqkv, g_qkv);
    cudaGetSymbolAddress((void**)&pctx, g_ctx);
    cudaGetSymbolAddress((void**)&px2,  g_x2);
    cudaGetSymbolAddress((void**)&pff,  g_ff);
    cudaGetSymbolAddress((void**)&pwq,  g_wq);
    cudaGetSymbolAddress((void**)&pwo,  g_wo);
    cudaGetSymbolAddress((void**)&pw1,  g_w1);
    cudaGetSymbolAddress((void**)&pw2,  g_w2);

    cudaFuncSetAttribute(tf32_gemm<0>, cudaFuncAttributeMaxDynamicSharedMemorySize, GEMM_SMEM);
    cudaFuncSetAttribute(tf32_gemm<1>, cudaFuncAttributeMaxDynamicSharedMemorySize, GEMM_SMEM);
    cudaFuncSetAttribute(tf32_gemm<2>, cudaFuncAttributeMaxDynamicSharedMemorySize, GEMM_SMEM);
    const int ATT_SMEM = (64 * 65 + 64 * 68 + 64 * 64 + 64 * 65) * 4;
    cudaFuncSetAttribute(attn_kernel,
                         cudaFuncAttributeMaxDynamicSharedMemorySize, ATT_SMEM);

    // 0) round weights to tf32
    round_kernel<<<3 * EMB * EMB / 4 / 256, 256>>>(qkvw, pwq, 3 * EMB * EMB / 4);
    round_kernel<<<EMB * EMB / 4 / 256, 256>>>(outw, pwo, EMB * EMB / 4);
    round_kernel<<<FF * EMB / 4 / 256, 256>>>(fc1w, pw1, FF * EMB / 4);
    round_kernel<<<EMB * FF / 4 / 256, 256>>>(fc2w, pw2, EMB * FF / 4);

    // 1) LN1 (tf32-rounded output)
    ln_kernel<<<BT, 256>>>(x, ln1w, ln1b, ph);
    // 2) QKV projection (fp32 out)
    tf32_gemm<0><<<dim3(3 * EMB / BN, BT / BM), 256, GEMM_SMEM>>>(
        ph, pwq, qkvb, nullptr, pqkv, BT, 3 * EMB, EMB);
    // 3) causal flash attention (tf32-rounded out)
    attn_kernel<<<dim3(4 * NH, TSEQ / 64), 128, ATT_SMEM>>>(pqkv, pctx);
    // 4) out projection + residual(x) (fp32 out)
    tf32_gemm<2><<<dim3(EMB / BN, BT / BM), 256, GEMM_SMEM>>>(
        pctx, pwo, outb, x, px2, BT, EMB, EMB);
    // 5) LN2 (tf32-rounded output)
    ln_kernel<<<BT, 256>>>(px2, ln2w, ln2b, ph);
    // 6) FC1 + GELU (tf32-rounded out)
    tf32_gemm<1><<<dim3(FF / BN, BT / BM), 256, GEMM_SMEM>>>(
        ph, pw1, fc1b, nullptr, pff, BT, FF, EMB);
    // 7) FC2 + residual(x2) -> d_out (fp32)
    tf32_gemm<2><<<dim3(EMB / BN, BT / BM), 256, GEMM_SMEM>>>(
        pff, pw2, fc2b, px2, out, BT, EMB, FF);
}

// round 15
// speedup vs baseline: 3.2515x; 1.4832x over previous
#include <cuda_runtime.h>
#include <cuda_fp16.h>
#include <math.h>
#include <cstdint>

// ---------------- problem constants ----------------
#define EMB  1024
#define NH   16
#define HD   64
#define FF   4096
#define TSEQ 1024
#define BT   4096          // B * T rows

// ---------------- GEMM tile config (fp16 single-pass) ----------------
#define BM 128
#define BN 128
#define BK 64              // 64 fp16 = 128 bytes per row (SW128 atom)
#define STAGES 3
#define STAGE_BYTES 32768  // A 16K + B 16K
#define GEMM_SMEM (STAGES * STAGE_BYTES)

// ---------------- scratch (no allocations allowed) ----------------
__device__ __half g_h  [BT * EMB];        // LN output (fp16)
__device__ float  g_qkv[BT * 3 * EMB];    // QKV (fp32, attn input)
__device__ __half g_ctx[BT * EMB];        // attention out (fp16)
__device__ float  g_x2 [BT * EMB];        // residual after attention (fp32)
__device__ __half g_ff [BT * FF];         // FC1+GELU out (fp16)
__device__ __half g_wq [3 * EMB * EMB];   // fp16 weights
__device__ __half g_wo [EMB * EMB];
__device__ __half g_w1 [FF * EMB];
__device__ __half g_w2 [EMB * FF];

// ---------------- helpers ----------------
__device__ __forceinline__ uint32_t smem_u32(const void* p) {
    uint32_t a;
    asm("{ .reg .u64 t; cvta.to.shared.u64 t, %1; cvt.u32.u64 %0, t; }"
        : "=r"(a) : "l"(p));
    return a;
}
#define SWZ128(o) ((o) ^ (((o) >> 3) & 0x70))

#define CP16(dst, src) \
    asm volatile("cp.async.cg.shared.global [%0], [%1], 16;" :: "r"(dst), "l"(src))
#define CP_COMMIT() asm volatile("cp.async.commit_group;" ::: "memory")
#define CP_WAIT1()  asm volatile("cp.async.wait_group 1;" ::: "memory")

#define LDSM4(r, addr)                                                         \
    asm volatile("ldmatrix.sync.aligned.m8n8.x4.shared.b16 {%0,%1,%2,%3}, [%4];" \
        : "=r"((r)[0]), "=r"((r)[1]), "=r"((r)[2]), "=r"((r)[3]) : "r"(addr))

__device__ __forceinline__ float gelu_f(float v) {
    return 0.5f * v * (1.0f + erff(v * 0.70710678118654752f));
}

// ---------------- weight fp16-convert kernel ----------------
__global__ __launch_bounds__(256)
void cvt_kernel(const float* __restrict__ w, __half* __restrict__ o, int n4)
{
    int i = blockIdx.x * 256 + threadIdx.x;
    if (i >= n4) return;
    float4 v = *(const float4*)(w + i * 4);
    __half h[4];
    h[0] = __float2half_rn(v.x); h[1] = __float2half_rn(v.y);
    h[2] = __float2half_rn(v.z); h[3] = __float2half_rn(v.w);
    *(uint2*)(o + i * 4) = *(uint2*)h;
}

// ---------------- LayerNorm (fp32 in, fp16 out) ----------------
__global__ __launch_bounds__(256)
void ln_kernel(const float* __restrict__ x, const float* __restrict__ w,
               const float* __restrict__ b, __half* __restrict__ out)
{
    int row = blockIdx.x;
    int tid = threadIdx.x;
    const float* xr = x + (size_t)row * EMB;
    float4 v = *(const float4*)(xr + tid * 4);
    float s  = v.x + v.y + v.z + v.w;
    float sq = v.x * v.x + v.y * v.y + v.z * v.z + v.w * v.w;
    #pragma unroll
    for (int o = 16; o > 0; o >>= 1) {
        s  += __shfl_xor_sync(0xffffffffu, s,  o);
        sq += __shfl_xor_sync(0xffffffffu, sq, o);
    }
    __shared__ float rs[8], rq[8];
    int wid = tid >> 5, lane = tid & 31;
    if (lane == 0) { rs[wid] = s; rq[wid] = sq; }
    __syncthreads();
    if (tid == 0) {
        float S = 0.f, Q = 0.f;
        #pragma unroll
        for (int i = 0; i < 8; i++) { S += rs[i]; Q += rq[i]; }
        rs[0] = S; rq[0] = Q;
    }
    __syncthreads();
    float mean = rs[0] * (1.f / EMB);
    float var  = rq[0] * (1.f / EMB) - mean * mean;
    float inv  = rsqrtf(var + 1e-5f);
    float4 wv = *(const float4*)(w + tid * 4);
    float4 bv = *(const float4*)(b + tid * 4);
    __half h[4];
    h[0] = __float2half_rn((v.x - mean) * inv * wv.x + bv.x);
    h[1] = __float2half_rn((v.y - mean) * inv * wv.y + bv.y);
    h[2] = __float2half_rn((v.z - mean) * inv * wv.z + bv.z);
    h[3] = __float2half_rn((v.w - mean) * inv * wv.w + bv.w);
    *(uint2*)(out + (size_t)row * EMB + tid * 4) = *(uint2*)h;
}

// ---------------- fp16 mma.sync GEMM (single pass) ----------------
// C[M,N] = A[M,K] @ W[N,K]^T + bias; A,W fp16.
// EPI 0: fp32 out (bias) | EPI 1: bias+GELU -> fp16 | EPI 2: bias+res -> fp32
__device__ __forceinline__ void fill_stage(uint32_t stage,
    const __half* __restrict__ A, const __half* __restrict__ W,
    int K, int c, int bm, int bn, int tid)
{
    const size_t a0 = (size_t)(bm * BM) * K + (size_t)c * BK;
    const size_t b0 = (size_t)(bn * BN) * K + (size_t)c * BK;
    #pragma unroll
    for (int i = 0; i < 4; i++) {
        int idx = tid + i * 256;
        int r = idx >> 3, s = idx & 7;
        uint32_t so = SWZ128((uint32_t)(r * 128 + s * 16));
        CP16(stage + so,          A + a0 + (size_t)r * K + s * 8);
        CP16(stage + 16384 + so,  W + b0 + (size_t)r * K + s * 8);
    }
}

__device__ __forceinline__ void mma_pass(float (&acc)[4][4][4],
                                         uint32_t (&a)[4][4], uint32_t (&b)[2][4])
{
    #pragma unroll
    for (int i = 0; i < 4; i++)
        #pragma unroll
        for (int j8 = 0; j8 < 4; j8++) {
            uint32_t b0 = b[j8 >> 1][(j8 & 1) * 2];
            uint32_t b1 = b[j8 >> 1][(j8 & 1) * 2 + 1];
            asm volatile(
                "mma.sync.aligned.m16n8k16.row.col.f32.f16.f16.f32 "
                "{%0,%1,%2,%3}, {%4,%5,%6,%7}, {%8,%9}, {%0,%1,%2,%3};"
                : "+f"(acc[i][j8][0]), "+f"(acc[i][j8][1]),
                  "+f"(acc[i][j8][2]), "+f"(acc[i][j8][3])
                : "r"(a[i][0]), "r"(a[i][1]), "r"(a[i][2]), "r"(a[i][3]),
                  "r"(b0), "r"(b1));
        }
}

__device__ __forceinline__ void compute_chunk(uint32_t stage, int wm, int wn,
                                              int lane, float (&acc)[4][4][4])
{
    const uint32_t sa = stage;
    const uint32_t sb = stage + 16384;
    const int mrow = lane & 7, msel = lane >> 3;
    const int arow = wm * 64 + (msel & 1) * 8 + mrow;   // + i*16
    const int akb  = msel >> 1;
    const int brow = wn * 32 + (msel >> 1) * 8 + mrow;  // + j*16
    const int bkb  = msel & 1;

    #pragma unroll
    for (int ks = 0; ks < 4; ks++) {
        uint32_t a[4][4], b[2][4];
        #pragma unroll
        for (int i = 0; i < 4; i++) {
            uint32_t off = SWZ128((uint32_t)(((arow + i * 16) << 7) +
                                             ((ks * 2 + akb) << 4)));
            LDSM4(a[i], sa + off);
        }
        #pragma unroll
        for (int j = 0; j < 2; j++) {
            uint32_t off = SWZ128((uint32_t)(((brow + j * 16) << 7) +
                                             ((ks * 2 + bkb) << 4)));
            LDSM4(b[j], sb + off);
        }
        mma_pass(acc, a, b);
    }
}

template<int EPI>
__global__ __launch_bounds__(256)
void h_gemm(const __half* __restrict__ A, const __half* __restrict__ W,
            const float* __restrict__ bias, const float* __restrict__ res,
            float* __restrict__ Cf, __half* __restrict__ Ch,
            int M, int N, int K)
{
    extern __shared__ char smraw[];
    const uint32_t sbase = smem_u32(smraw);
    const int tid = threadIdx.x;
    const int bm = blockIdx.y, bn = blockIdx.x;
    const int wid = tid >> 5, lane = tid & 31;
    const int wm = wid & 1, wn = wid >> 1;
    const int NC = K >> 6;

    float acc[4][4][4];
    #pragma unroll
    for (int i = 0; i < 4; i++)
        #pragma unroll
        for (int j = 0; j < 4; j++)
            #pragma unroll
            for (int k = 0; k < 4; k++) acc[i][j][k] = 0.f;

    fill_stage(sbase,               A, W, K, 0, bm, bn, tid);
    CP_COMMIT();
    fill_stage(sbase + STAGE_BYTES, A, W, K, 1, bm, bn, tid);
    CP_COMMIT();

    for (int c = 0; c < NC; ++c) {
        CP_WAIT1();
        __syncthreads();
        if (c + 2 < NC)
            fill_stage(sbase + ((c + 2) % STAGES) * STAGE_BYTES,
                       A, W, K, c + 2, bm, bn, tid);
        CP_COMMIT();
        compute_chunk(sbase + (c % STAGES) * STAGE_BYTES, wm, wn, lane, acc);
    }

    // ---- epilogue (m16n8 C layout) ----
    const int row0 = bm * BM + wm * 64 + (lane >> 2);
    const int colw = bn * BN + wn * 32 + (lane & 3) * 2;
    #pragma unroll
    for (int i = 0; i < 4; i++) {
        #pragma unroll
        for (int j8 = 0; j8 < 4; j8++) {
            const int col = colw + j8 * 8;
            float2 bb = *(const float2*)(bias + col);
            float v0 = acc[i][j8][0] + bb.x;
            float v1 = acc[i][j8][1] + bb.y;
            float v2 = acc[i][j8][2] + bb.x;
            float v3 = acc[i][j8][3] + bb.y;
            const size_t o0 = (size_t)(row0 + i * 16) * N + col;
            const size_t o1 = o0 + (size_t)8 * N;
            if (EPI == 1) {
                __half h0[2], h1[2];
                h0[0] = __float2half_rn(gelu_f(v0));
                h0[1] = __float2half_rn(gelu_f(v1));
                h1[0] = __float2half_rn(gelu_f(v2));
                h1[1] = __float2half_rn(gelu_f(v3));
                *(uint32_t*)(Ch + o0) = *(uint32_t*)h0;
                *(uint32_t*)(Ch + o1) = *(uint32_t*)h1;
            } else {
                if (EPI == 2) {
                    float2 r0v = *(const float2*)(res + o0);
                    float2 r1v = *(const float2*)(res + o1);
                    v0 += r0v.x; v1 += r0v.y; v2 += r1v.x; v3 += r1v.y;
                }
                float2 w0 = {v0, v1}, w1 = {v2, v3};
                *(float2*)(Cf + o0) = w0;
                *(float2*)(Cf + o1) = w1;
            }
        }
    }
}

// ---------------- flash attention (fp32, causal), fp16 output ----------------
__global__ __launch_bounds__(128)
void attn_kernel(const float* __restrict__ qkv, __half* __restrict__ ctx)
{
    extern __shared__ float sm[];
    float (*Qs)[65]  = (float(*)[65])sm;
    float (*Kst)[68] = (float(*)[68])(sm + 64 * 65);
    float (*Vs)[64]  = (float(*)[64])(sm + 64 * 65 + 64 * 68);
    float (*Ps)[65]  = (float(*)[65])(sm + 64 * 65 + 64 * 68 + 64 * 64);

    const int b  = blockIdx.x >> 4;
    const int h  = blockIdx.x & 15;
    const int qt = blockIdx.y;
    const int tid = threadIdx.x;
    const int r   = tid >> 1;
    const int off = (tid & 1) * 32;
    const int q0  = qt * 64;
    const size_t rowstride = 3 * EMB;

    const float* qg = qkv + (size_t)(b * TSEQ + q0 + r) * rowstride + h * HD + off;
    #pragma unroll
    for (int i = 0; i < 32; i += 4) {
        float4 v = *(const float4*)(qg + i);
        Qs[r][off + i + 0] = v.x * 0.125f;
        Qs[r][off + i + 1] = v.y * 0.125f;
        Qs[r][off + i + 2] = v.z * 0.125f;
        Qs[r][off + i + 3] = v.w * 0.125f;
    }

    float m_run = -1e30f, l_run = 0.f;
    float O[32];
    #pragma unroll
    for (int i = 0; i < 32; i++) O[i] = 0.f;

    for (int j = 0; j <= qt; ++j) {
        const int k0 = j * 64;
        __syncthreads();
        {
            const int kc = tid >> 1;
            const float* kg = qkv + (size_t)(b * TSEQ + k0 + kc) * rowstride + EMB + h * HD + off;
            const float* vg = kg + EMB;
            #pragma unroll
            for (int i = 0; i < 32; i += 4) {
                float4 kv = *(const float4*)(kg + i);
                Kst[off + i + 0][kc] = kv.x;
                Kst[off + i + 1][kc] = kv.y;
                Kst[off + i + 2][kc] = kv.z;
                Kst[off + i + 3][kc] = kv.w;
                *(float4*)(&Vs[kc][off + i]) = *(const float4*)(vg + i);
            }
        }
        __syncthreads();

        float s[32];
        #pragma unroll
        for (int c = 0; c < 32; c++) s[c] = 0.f;
        #pragma unroll 4
        for (int d = 0; d < 64; ++d) {
            float q = Qs[r][d];
            #pragma unroll
            for (int c = 0; c < 32; c += 4) {
                float4 kk = *(const float4*)(&Kst[d][off + c]);
                s[c + 0] += q * kk.x;
                s[c + 1] += q * kk.y;
                s[c + 2] += q * kk.z;
                s[c + 3] += q * kk.w;
            }
        }
        if (j == qt) {
            #pragma unroll
            for (int c = 0; c < 32; c++)
                if (k0 + off + c > q0 + r) s[c] = -1e30f;
        }

        float mx = s[0];
        #pragma unroll
        for (int c = 1; c < 32; c++) mx = fmaxf(mx, s[c]);
        mx = fmaxf(mx, __shfl_xor_sync(0xffffffffu, mx, 1));
        float m_new = fmaxf(m_run, mx);
        float alpha = __expf(m_run - m_new);
        float lsum = 0.f;
        #pragma unroll
        for (int c = 0; c < 32; c++) {
            float p = __expf(s[c] - m_new);
            lsum += p;
            Ps[r][off + c] = p;
        }
        lsum += __shfl_xor_sync(0xffffffffu, lsum, 1);
        l_run = l_run * alpha + lsum;
        m_run = m_new;
        #pragma unroll
        for (int i = 0; i < 32; i++) O[i] *= alpha;
        __syncthreads();

        #pragma unroll 4
        for (int kc = 0; kc < 64; ++kc) {
            float p = Ps[r][kc];
            #pragma unroll
            for (int i = 0; i < 32; i += 4) {
                float4 vv = *(const float4*)(&Vs[kc][off + i]);
                O[i + 0] += p * vv.x;
                O[i + 1] += p * vv.y;
                O[i + 2] += p * vv.z;
                O[i + 3] += p * vv.w;
            }
        }
    }

    const float inv = 1.f / l_run;
    __half* og = ctx + (size_t)(b * TSEQ + q0 + r) * EMB + h * HD + off;
    #pragma unroll
    for (int i = 0; i < 32; i += 4) {
        __half hb[4];
        hb[0] = __float2half_rn(O[i + 0] * inv);
        hb[1] = __float2half_rn(O[i + 1] * inv);
        hb[2] = __float2half_rn(O[i + 2] * inv);
        hb[3] = __float2half_rn(O[i + 3] * inv);
        *(uint2*)(og + i) = *(uint2*)hb;
    }
}

// ---------------- launch ----------------
extern "C" void kernel_launch(void* const* d_in, const int* in_sizes, int n_in,
                              void* d_out, int out_size)
{
    const float* x    = (const float*)d_in[0];
    const float* ln1w = (const float*)d_in[1];
    const float* ln1b = (const float*)d_in[2];
    const float* ln2w = (const float*)d_in[3];
    const float* ln2b = (const float*)d_in[4];
    const float* qkvw = (const float*)d_in[5];
    const float* qkvb = (const float*)d_in[6];
    const float* outw = (const float*)d_in[7];
    const float* outb = (const float*)d_in[8];
    const float* fc1w = (const float*)d_in[9];
    const float* fc1b = (const float*)d_in[10];
    const float* fc2w = (const float*)d_in[11];
    const float* fc2b = (const float*)d_in[12];
    float* out = (float*)d_out;

    __half *ph, *pctx, *pff, *pwq, *pwo, *pw1, *pw2;
    float *pqkv, *px2;
    cudaGetSymbolAddress((void**)&ph,   g_h);
    cudaGetSymbolAddress((void**)&pqkv, g_qkv);
    cudaGetSymbolAddress((void**)&pctx, g_ctx);
    cudaGetSymbolAddress((void**)&px2,  g_x2);
    cudaGetSymbolAddress((void**)&pff,  g_ff);
    cudaGetSymbolAddress((void**)&pwq,  g_wq);
    cudaGetSymbolAddress((void**)&pwo,  g_wo);
    cudaGetSymbolAddress((void**)&pw1,  g_w1);
    cudaGetSymbolAddress((void**)&pw2,  g_w2);

    cudaFuncSetAttribute(h_gemm<0>, cudaFuncAttributeMaxDynamicSharedMemorySize, GEMM_SMEM);
    cudaFuncSetAttribute(h_gemm<1>, cudaFuncAttributeMaxDynamicSharedMemorySize, GEMM_SMEM);
    cudaFuncSetAttribute(h_gemm<2>, cudaFuncAttributeMaxDynamicSharedMemorySize, GEMM_SMEM);
    const int ATT_SMEM = (64 * 65 + 64 * 68 + 64 * 64 + 64 * 65) * 4;
    cudaFuncSetAttribute(attn_kernel,
                         cudaFuncAttributeMaxDynamicSharedMemorySize, ATT_SMEM);

    // 0) convert weights to fp16
    cvt_kernel<<<3 * EMB * EMB / 4 / 256, 256>>>(qkvw, pwq, 3 * EMB * EMB / 4);
    cvt_kernel<<<EMB * EMB / 4 / 256, 256>>>(outw, pwo, EMB * EMB / 4);
    cvt_kernel<<<FF * EMB / 4 / 256, 256>>>(fc1w, pw1, FF * EMB / 4);
    cvt_kernel<<<EMB * FF / 4 / 256, 256>>>(fc2w, pw2, EMB * FF / 4);

    // 1) LN1 (fp16 out)
    ln_kernel<<<BT, 256>>>(x, ln1w, ln1b, ph);
    // 2) QKV projection (fp32 out)
    h_gemm<0><<<dim3(3 * EMB / BN, BT / BM), 256, GEMM_SMEM>>>(
        ph, pwq, qkvb, nullptr, pqkv, nullptr, BT, 3 * EMB, EMB);
    // 3) causal flash attention (fp16 out)
    attn_kernel<<<dim3(4 * NH, TSEQ / 64), 128, ATT_SMEM>>>(pqkv, pctx);
    // 4) out projection + residual(x) (fp32 out)
    h_gemm<2><<<dim3(EMB / BN, BT / BM), 256, GEMM_SMEM>>>(
        pctx, pwo, outb, x, px2, nullptr, BT, EMB, EMB);
    // 5) LN2 (fp16 out)
    ln_kernel<<<BT, 256>>>(px2, ln2w, ln2b, ph);
    // 6) FC1 + GELU (fp16 out)
    h_gemm<1><<<dim3(FF / BN, BT / BM), 256, GEMM_SMEM>>>(
        ph, pw1, fc1b, nullptr, nullptr, pff, BT, FF, EMB);
    // 7) FC2 + residual(x2) -> d_out (fp32)
    h_gemm<2><<<dim3(EMB / BN, BT / BM), 256, GEMM_SMEM>>>(
        pff, pw2, fc2b, px2, out, nullptr, BT, EMB, FF);
}

// round 16
// speedup vs baseline: 8.3854x; 2.5790x over previous
#include <cuda_runtime.h>
#include <cuda_fp16.h>
#include <math.h>
#include <cstdint>

// ---------------- problem constants ----------------
#define EMB  1024
#define NH   16
#define HD   64
#define FF   4096
#define TSEQ 1024
#define BT   4096          // B * T rows

// ---------------- GEMM tile config (fp16 single-pass) ----------------
#define BM 128
#define BN 128
#define BK 64              // 64 fp16 = 128 bytes per row (SW128 atom)
#define STAGES 3
#define STAGE_BYTES 32768  // A 16K + B 16K
#define GEMM_SMEM (STAGES * STAGE_BYTES)

// ---------------- attention config ----------------
#define ATT_SMEM (8192 + 3 * 16384)   // Q + 3 stages of (K 8K + V 8K)

// ---------------- scratch (no allocations allowed) ----------------
__device__ __half g_h   [BT * EMB];        // LN output (fp16)
__device__ __half g_qkvh[BT * 3 * EMB];    // QKV (fp16, q pre-scaled)
__device__ __half g_ctx [BT * EMB];        // attention out (fp16)
__device__ float  g_x2  [BT * EMB];        // residual after attention (fp32)
__device__ __half g_ff  [BT * FF];         // FC1+GELU out (fp16)
__device__ __half g_wq  [3 * EMB * EMB];   // fp16 weights
__device__ __half g_wo  [EMB * EMB];
__device__ __half g_w1  [FF * EMB];
__device__ __half g_w2  [EMB * FF];

// ---------------- helpers ----------------
__device__ __forceinline__ uint32_t smem_u32(const void* p) {
    uint32_t a;
    asm("{ .reg .u64 t; cvta.to.shared.u64 t, %1; cvt.u32.u64 %0, t; }"
        : "=r"(a) : "l"(p));
    return a;
}
#define SWZ128(o) ((o) ^ (((o) >> 3) & 0x70))

#define CP16(dst, src) \
    asm volatile("cp.async.cg.shared.global [%0], [%1], 16;" :: "r"(dst), "l"(src))
#define CP_COMMIT() asm volatile("cp.async.commit_group;" ::: "memory")
#define CP_WAIT1()  asm volatile("cp.async.wait_group 1;" ::: "memory")

#define LDSM4(r, addr)                                                         \
    asm volatile("ldmatrix.sync.aligned.m8n8.x4.shared.b16 {%0,%1,%2,%3}, [%4];" \
        : "=r"((r)[0]), "=r"((r)[1]), "=r"((r)[2]), "=r"((r)[3]) : "r"(addr))
#define LDSM4T(r, addr)                                                        \
    asm volatile("ldmatrix.sync.aligned.m8n8.x4.trans.shared.b16 {%0,%1,%2,%3}, [%4];" \
        : "=r"((r)[0]), "=r"((r)[1]), "=r"((r)[2]), "=r"((r)[3]) : "r"(addr))

#define HMMA(d, a, b0v, b1v)                                                   \
    asm volatile("mma.sync.aligned.m16n8k16.row.col.f32.f16.f16.f32 "          \
        "{%0,%1,%2,%3}, {%4,%5,%6,%7}, {%8,%9}, {%0,%1,%2,%3};"                \
        : "+f"((d)[0]), "+f"((d)[1]), "+f"((d)[2]), "+f"((d)[3])               \
        : "r"((a)[0]), "r"((a)[1]), "r"((a)[2]), "r"((a)[3]),                  \
          "r"(b0v), "r"(b1v))

__device__ __forceinline__ float gelu_f(float v) {
    return 0.5f * v * (1.0f + erff(v * 0.70710678118654752f));
}
__device__ __forceinline__ uint32_t pack2(float lo, float hi) {
    __half2 h = __floats2half2_rn(lo, hi);
    return *(uint32_t*)&h;
}

// ---------------- weight fp16-convert kernel ----------------
__global__ __launch_bounds__(256)
void cvt_kernel(const float* __restrict__ w, __half* __restrict__ o, int n4)
{
    int i = blockIdx.x * 256 + threadIdx.x;
    if (i >= n4) return;
    float4 v = *(const float4*)(w + i * 4);
    __half h[4];
    h[0] = __float2half_rn(v.x); h[1] = __float2half_rn(v.y);
    h[2] = __float2half_rn(v.z); h[3] = __float2half_rn(v.w);
    *(uint2*)(o + i * 4) = *(uint2*)h;
}

// ---------------- LayerNorm (fp32 in, fp16 out) ----------------
__global__ __launch_bounds__(256)
void ln_kernel(const float* __restrict__ x, const float* __restrict__ w,
               const float* __restrict__ b, __half* __restrict__ out)
{
    int row = blockIdx.x;
    int tid = threadIdx.x;
    const float* xr = x + (size_t)row * EMB;
    float4 v = *(const float4*)(xr + tid * 4);
    float s  = v.x + v.y + v.z + v.w;
    float sq = v.x * v.x + v.y * v.y + v.z * v.z + v.w * v.w;
    #pragma unroll
    for (int o = 16; o > 0; o >>= 1) {
        s  += __shfl_xor_sync(0xffffffffu, s,  o);
        sq += __shfl_xor_sync(0xffffffffu, sq, o);
    }
    __shared__ float rs[8], rq[8];
    int wid = tid >> 5, lane = tid & 31;
    if (lane == 0) { rs[wid] = s; rq[wid] = sq; }
    __syncthreads();
    if (tid == 0) {
        float S = 0.f, Q = 0.f;
        #pragma unroll
        for (int i = 0; i < 8; i++) { S += rs[i]; Q += rq[i]; }
        rs[0] = S; rq[0] = Q;
    }
    __syncthreads();
    float mean = rs[0] * (1.f / EMB);
    float var  = rq[0] * (1.f / EMB) - mean * mean;
    float inv  = rsqrtf(var + 1e-5f);
    float4 wv = *(const float4*)(w + tid * 4);
    float4 bv = *(const float4*)(b + tid * 4);
    __half h[4];
    h[0] = __float2half_rn((v.x - mean) * inv * wv.x + bv.x);
    h[1] = __float2half_rn((v.y - mean) * inv * wv.y + bv.y);
    h[2] = __float2half_rn((v.z - mean) * inv * wv.z + bv.z);
    h[3] = __float2half_rn((v.w - mean) * inv * wv.w + bv.w);
    *(uint2*)(out + (size_t)row * EMB + tid * 4) = *(uint2*)h;
}

// ---------------- fp16 mma.sync GEMM ----------------
// EPI 0: fp32 (bias) | 1: bias+GELU->fp16 | 2: bias+res->fp32 | 3: fp16, q cols scaled
__device__ __forceinline__ void fill_stage(uint32_t stage,
    const __half* __restrict__ A, const __half* __restrict__ W,
    int K, int c, int bm, int bn, int tid)
{
    const size_t a0 = (size_t)(bm * BM) * K + (size_t)c * BK;
    const size_t b0 = (size_t)(bn * BN) * K + (size_t)c * BK;
    #pragma unroll
    for (int i = 0; i < 4; i++) {
        int idx = tid + i * 256;
        int r = idx >> 3, s = idx & 7;
        uint32_t so = SWZ128((uint32_t)(r * 128 + s * 16));
        CP16(stage + so,          A + a0 + (size_t)r * K + s * 8);
        CP16(stage + 16384 + so,  W + b0 + (size_t)r * K + s * 8);
    }
}

__device__ __forceinline__ void mma_pass(float (&acc)[4][4][4],
                                         uint32_t (&a)[4][4], uint32_t (&b)[2][4])
{
    #pragma unroll
    for (int i = 0; i < 4; i++)
        #pragma unroll
        for (int j8 = 0; j8 < 4; j8++) {
            uint32_t b0 = b[j8 >> 1][(j8 & 1) * 2];
            uint32_t b1 = b[j8 >> 1][(j8 & 1) * 2 + 1];
            HMMA(acc[i][j8], a[i], b0, b1);
        }
}

__device__ __forceinline__ void compute_chunk(uint32_t stage, int wm, int wn,
                                              int lane, float (&acc)[4][4][4])
{
    const uint32_t sa = stage;
    const uint32_t sb = stage + 16384;
    const int mrow = lane & 7, msel = lane >> 3;
    const int arow = wm * 64 + (msel & 1) * 8 + mrow;
    const int akb  = msel >> 1;
    const int brow = wn * 32 + (msel >> 1) * 8 + mrow;
    const int bkb  = msel & 1;

    #pragma unroll
    for (int ks = 0; ks < 4; ks++) {
        uint32_t a[4][4], b[2][4];
        #pragma unroll
        for (int i = 0; i < 4; i++) {
            uint32_t off = SWZ128((uint32_t)(((arow + i * 16) << 7) +
                                             ((ks * 2 + akb) << 4)));
            LDSM4(a[i], sa + off);
        }
        #pragma unroll
        for (int j = 0; j < 2; j++) {
            uint32_t off = SWZ128((uint32_t)(((brow + j * 16) << 7) +
                                             ((ks * 2 + bkb) << 4)));
            LDSM4(b[j], sb + off);
        }
        mma_pass(acc, a, b);
    }
}

template<int EPI>
__global__ __launch_bounds__(256)
void h_gemm(const __half* __restrict__ A, const __half* __restrict__ W,
            const float* __restrict__ bias, const float* __restrict__ res,
            float* __restrict__ Cf, __half* __restrict__ Ch,
            int M, int N, int K)
{
    extern __shared__ char smraw[];
    const uint32_t sbase = smem_u32(smraw);
    const int tid = threadIdx.x;
    const int bm = blockIdx.y, bn = blockIdx.x;
    const int wid = tid >> 5, lane = tid & 31;
    const int wm = wid & 1, wn = wid >> 1;
    const int NC = K >> 6;

    float acc[4][4][4];
    #pragma unroll
    for (int i = 0; i < 4; i++)
        #pragma unroll
        for (int j = 0; j < 4; j++)
            #pragma unroll
            for (int k = 0; k < 4; k++) acc[i][j][k] = 0.f;

    fill_stage(sbase,               A, W, K, 0, bm, bn, tid);
    CP_COMMIT();
    fill_stage(sbase + STAGE_BYTES, A, W, K, 1, bm, bn, tid);
    CP_COMMIT();

    for (int c = 0; c < NC; ++c) {
        CP_WAIT1();
        __syncthreads();
        if (c + 2 < NC)
            fill_stage(sbase + ((c + 2) % STAGES) * STAGE_BYTES,
                       A, W, K, c + 2, bm, bn, tid);
        CP_COMMIT();
        compute_chunk(sbase + (c % STAGES) * STAGE_BYTES, wm, wn, lane, acc);
    }

    const int row0 = bm * BM + wm * 64 + (lane >> 2);
    const int colw = bn * BN + wn * 32 + (lane & 3) * 2;
    #pragma unroll
    for (int i = 0; i < 4; i++) {
        #pragma unroll
        for (int j8 = 0; j8 < 4; j8++) {
            const int col = colw + j8 * 8;
            float2 bb = *(const float2*)(bias + col);
            float v0 = acc[i][j8][0] + bb.x;
            float v1 = acc[i][j8][1] + bb.y;
            float v2 = acc[i][j8][2] + bb.x;
            float v3 = acc[i][j8][3] + bb.y;
            const size_t o0 = (size_t)(row0 + i * 16) * N + col;
            const size_t o1 = o0 + (size_t)8 * N;
            if (EPI == 1 || EPI == 3) {
                if (EPI == 3 && col < EMB) {
                    v0 *= 0.125f; v1 *= 0.125f; v2 *= 0.125f; v3 *= 0.125f;
                }
                if (EPI == 1) {
                    v0 = gelu_f(v0); v1 = gelu_f(v1);
                    v2 = gelu_f(v2); v3 = gelu_f(v3);
                }
                uint32_t p0 = pack2(v0, v1), p1 = pack2(v2, v3);
                *(uint32_t*)(Ch + o0) = p0;
                *(uint32_t*)(Ch + o1) = p1;
            } else {
                if (EPI == 2) {
                    float2 r0v = *(const float2*)(res + o0);
                    float2 r1v = *(const float2*)(res + o1);
                    v0 += r0v.x; v1 += r0v.y; v2 += r1v.x; v3 += r1v.y;
                }
                float2 w0 = {v0, v1}, w1 = {v2, v3};
                *(float2*)(Cf + o0) = w0;
                *(float2*)(Cf + o1) = w1;
            }
        }
    }
}

// ---------------- fp16 tensor-core flash attention ----------------
// grid (qt=16, bh=64), block 128. Warp w handles q rows q0+w*16..+15.
// smem: Q[64][64]h @0, stage s: K @8192+s*16384, V @+8192.
__device__ __forceinline__ void fa_fill_kv(uint32_t kbase,
    const __half* __restrict__ qkv, int b, int h, int t, int tid)
{
    #pragma unroll
    for (int i = 0; i < 4; i++) {
        int idx = tid + i * 128;
        int r = idx >> 3, s = idx & 7;
        const __half* src = qkv + (size_t)(b * TSEQ + t * 64 + r) * (3 * EMB)
                          + EMB + h * HD + s * 8;
        uint32_t so = SWZ128((uint32_t)(r * 128 + s * 16));
        CP16(kbase + so,        src);        // K
        CP16(kbase + 8192 + so, src + EMB);  // V
    }
}

__global__ __launch_bounds__(128)
void fattn(const __half* __restrict__ qkv, __half* __restrict__ ctx)
{
    extern __shared__ char smraw[];
    const uint32_t sbase = smem_u32(smraw);
    const int qt = blockIdx.x;
    const int b  = blockIdx.y >> 4;
    const int h  = blockIdx.y & 15;
    const int tid = threadIdx.x;
    const int wid = tid >> 5, lane = tid & 31;
    const int q0 = qt * 64;
    const int NT = qt + 1;
    const int mrow = lane & 7, msel = lane >> 3;

    // prologue: Q + stage0 as group0; stage1 as group1
    #pragma unroll
    for (int i = 0; i < 4; i++) {
        int idx = tid + i * 128;
        int r = idx >> 3, s = idx & 7;
        const __half* src = qkv + (size_t)(b * TSEQ + q0 + r) * (3 * EMB)
                          + h * HD + s * 8;
        CP16(sbase + SWZ128((uint32_t)(r * 128 + s * 16)), src);
    }
    fa_fill_kv(sbase + 8192, qkv, b, h, 0, tid);
    CP_COMMIT();
    if (NT > 1) fa_fill_kv(sbase + 8192 + 16384, qkv, b, h, 1, tid);
    CP_COMMIT();

    uint32_t qf[4][4];
    float o[8][4];
    #pragma unroll
    for (int j = 0; j < 8; j++)
        #pragma unroll
        for (int k = 0; k < 4; k++) o[j][k] = 0.f;
    float m_run[2] = {-1e30f, -1e30f};
    float l_run[2] = {0.f, 0.f};

    const int arow = wid * 16 + (msel & 1) * 8 + mrow;
    const int akb  = msel >> 1;

    for (int t = 0; t < NT; ++t) {
        CP_WAIT1();
        __syncthreads();
        if (t + 2 < NT)
            fa_fill_kv(sbase + 8192 + ((t + 2) % 3) * 16384, qkv, b, h, t + 2, tid);
        CP_COMMIT();
        if (t == 0) {
            #pragma unroll
            for (int ks = 0; ks < 4; ks++)
                LDSM4(qf[ks], sbase + SWZ128((uint32_t)((arow << 7) +
                                                        ((ks * 2 + akb) << 4))));
        }
        const uint32_t Kb = sbase + 8192 + (t % 3) * 16384;
        const uint32_t Vb = Kb + 8192;

        // ---- S = Q K^T ----
        float s[8][4];
        #pragma unroll
        for (int j = 0; j < 8; j++)
            #pragma unroll
            for (int k = 0; k < 4; k++) s[j][k] = 0.f;
        const int brow_b = (msel >> 1) * 8 + mrow;
        const int bkb    = msel & 1;
        #pragma unroll
        for (int ks = 0; ks < 4; ks++) {
            uint32_t kb[4][4];
            #pragma unroll
            for (int g = 0; g < 4; g++)
                LDSM4(kb[g], Kb + SWZ128((uint32_t)(((g * 16 + brow_b) << 7) +
                                                    ((ks * 2 + bkb) << 4))));
            #pragma unroll
            for (int j = 0; j < 8; j++)
                HMMA(s[j], qf[ks], kb[j >> 1][(j & 1) * 2],
                     kb[j >> 1][(j & 1) * 2 + 1]);
        }

        // ---- causal mask (diagonal tile only) ----
        if (t == qt) {
            const int r0 = q0 + wid * 16 + (lane >> 2);
            const int r1 = r0 + 8;
            #pragma unroll
            for (int j = 0; j < 8; j++) {
                int kv0 = t * 64 + j * 8 + (lane & 3) * 2;
                if (kv0     > r0) s[j][0] = -1e30f;
                if (kv0 + 1 > r0) s[j][1] = -1e30f;
                if (kv0     > r1) s[j][2] = -1e30f;
                if (kv0 + 1 > r1) s[j][3] = -1e30f;
            }
        }

        // ---- online softmax ----
        float alpha[2];
        #pragma unroll
        for (int r = 0; r < 2; r++) {
            float mx = -1e30f;
            #pragma unroll
            for (int j = 0; j < 8; j++)
                mx = fmaxf(mx, fmaxf(s[j][r * 2], s[j][r * 2 + 1]));
            mx = fmaxf(mx, __shfl_xor_sync(0xffffffffu, mx, 1));
            mx = fmaxf(mx, __shfl_xor_sync(0xffffffffu, mx, 2));
            float m_new = fmaxf(m_run[r], mx);
            alpha[r] = __expf(m_run[r] - m_new);
            m_run[r] = m_new;
        }
        float lad0 = 0.f, lad1 = 0.f;
        #pragma unroll
        for (int j = 0; j < 8; j++) {
            s[j][0] = __expf(s[j][0] - m_run[0]);
            s[j][1] = __expf(s[j][1] - m_run[0]);
            s[j][2] = __expf(s[j][2] - m_run[1]);
            s[j][3] = __expf(s[j][3] - m_run[1]);
            lad0 += s[j][0] + s[j][1];
            lad1 += s[j][2] + s[j][3];
        }
        lad0 += __shfl_xor_sync(0xffffffffu, lad0, 1);
        lad0 += __shfl_xor_sync(0xffffffffu, lad0, 2);
        lad1 += __shfl_xor_sync(0xffffffffu, lad1, 1);
        lad1 += __shfl_xor_sync(0xffffffffu, lad1, 2);
        l_run[0] = l_run[0] * alpha[0] + lad0;
        l_run[1] = l_run[1] * alpha[1] + lad1;
        #pragma unroll
        for (int j = 0; j < 8; j++) {
            o[j][0] *= alpha[0]; o[j][1] *= alpha[0];
            o[j][2] *= alpha[1]; o[j][3] *= alpha[1];
        }

        // ---- O += P V ----
        #pragma unroll
        for (int kt = 0; kt < 4; kt++) {
            uint32_t a[4];
            a[0] = pack2(s[2 * kt][0],     s[2 * kt][1]);
            a[1] = pack2(s[2 * kt][2],     s[2 * kt][3]);
            a[2] = pack2(s[2 * kt + 1][0], s[2 * kt + 1][1]);
            a[3] = pack2(s[2 * kt + 1][2], s[2 * kt + 1][3]);
            const int vrow = kt * 16 + (msel & 1) * 8 + mrow;
            const int vcol = (msel >> 1) * 8;
            #pragma unroll
            for (int g = 0; g < 4; g++) {
                uint32_t vb[4];
                LDSM4T(vb, Vb + SWZ128((uint32_t)((vrow << 7) +
                                                  ((g * 16 + vcol) << 1))));
                HMMA(o[2 * g],     a, vb[0], vb[1]);
                HMMA(o[2 * g + 1], a, vb[2], vb[3]);
            }
        }
    }

    // ---- write ctx (fp16) ----
    const float inv0 = 1.f / l_run[0];
    const float inv1 = 1.f / l_run[1];
    const size_t tok0 = (size_t)(b * TSEQ + q0 + wid * 16 + (lane >> 2));
    #pragma unroll
    for (int j = 0; j < 8; j++) {
        const int col = h * HD + j * 8 + (lane & 3) * 2;
        uint32_t p0 = pack2(o[j][0] * inv0, o[j][1] * inv0);
        uint32_t p1 = pack2(o[j][2] * inv1, o[j][3] * inv1);
        *(uint32_t*)(ctx + tok0 * EMB + col)       = p0;
        *(uint32_t*)(ctx + (tok0 + 8) * EMB + col) = p1;
    }
}

// ---------------- launch ----------------
extern "C" void kernel_launch(void* const* d_in, const int* in_sizes, int n_in,
                              void* d_out, int out_size)
{
    const float* x    = (const float*)d_in[0];
    const float* ln1w = (const float*)d_in[1];
    const float* ln1b = (const float*)d_in[2];
    const float* ln2w = (const float*)d_in[3];
    const float* ln2b = (const float*)d_in[4];
    const float* qkvw = (const float*)d_in[5];
    const float* qkvb = (const float*)d_in[6];
    const float* outw = (const float*)d_in[7];
    const float* outb = (const float*)d_in[8];
    const float* fc1w = (const float*)d_in[9];
    const float* fc1b = (const float*)d_in[10];
    const float* fc2w = (const float*)d_in[11];
    const float* fc2b = (const float*)d_in[12];
    float* out = (float*)d_out;

    __half *ph, *pqkvh, *pctx, *pff, *pwq, *pwo, *pw1, *pw2;
    float *px2;
    cudaGetSymbolAddress((void**)&ph,    g_h);
    cudaGetSymbolAddress((void**)&pqkvh, g_qkvh);
    cudaGetSymbolAddress((void**)&pctx,  g_ctx);
    cudaGetSymbolAddress((void**)&px2,   g_x2);
    cudaGetSymbolAddress((void**)&pff,   g_ff);
    cudaGetSymbolAddress((void**)&pwq,   g_wq);
    cudaGetSymbolAddress((void**)&pwo,   g_wo);
    cudaGetSymbolAddress((void**)&pw1,   g_w1);
    cudaGetSymbolAddress((void**)&pw2,   g_w2);

    cudaFuncSetAttribute(h_gemm<0>, cudaFuncAttributeMaxDynamicSharedMemorySize, GEMM_SMEM);
    cudaFuncSetAttribute(h_gemm<1>, cudaFuncAttributeMaxDynamicSharedMemorySize, GEMM_SMEM);
    cudaFuncSetAttribute(h_gemm<2>, cudaFuncAttributeMaxDynamicSharedMemorySize, GEMM_SMEM);
    cudaFuncSetAttribute(h_gemm<3>, cudaFuncAttributeMaxDynamicSharedMemorySize, GEMM_SMEM);
    cudaFuncSetAttribute(fattn, cudaFuncAttributeMaxDynamicSharedMemorySize, ATT_SMEM);

    // 0) convert weights to fp16
    cvt_kernel<<<3 * EMB * EMB / 4 / 256, 256>>>(qkvw, pwq, 3 * EMB * EMB / 4);
    cvt_kernel<<<EMB * EMB / 4 / 256, 256>>>(outw, pwo, EMB * EMB / 4);
    cvt_kernel<<<FF * EMB / 4 / 256, 256>>>(fc1w, pw1, FF * EMB / 4);
    cvt_kernel<<<EMB * FF / 4 / 256, 256>>>(fc2w, pw2, EMB * FF / 4);

    // 1) LN1 (fp16 out)
    ln_kernel<<<BT, 256>>>(x, ln1w, ln1b, ph);
    // 2) QKV projection -> fp16, q pre-scaled by 1/8
    h_gemm<3><<<dim3(3 * EMB / BN, BT / BM), 256, GEMM_SMEM>>>(
        ph, pwq, qkvb, nullptr, nullptr, pqkvh, BT, 3 * EMB, EMB);
    // 3) fp16 tensor-core flash attention
    fattn<<<dim3(TSEQ / 64, 4 * NH), 128, ATT_SMEM>>>(pqkvh, pctx);
    // 4) out projection + residual(x) (fp32 out)
    h_gemm<2><<<dim3(EMB / BN, BT / BM), 256, GEMM_SMEM>>>(
        pctx, pwo, outb, x, px2, nullptr, BT, EMB, EMB);
    // 5) LN2 (fp16 out)
    ln_kernel<<<BT, 256>>>(px2, ln2w, ln2b, ph);
    // 6) FC1 + GELU (fp16 out)
    h_gemm<1><<<dim3(FF / BN, BT / BM), 256, GEMM_SMEM>>>(
        ph, pw1, fc1b, nullptr, nullptr, pff, BT, FF, EMB);
    // 7) FC2 + residual(x2) -> d_out (fp32)
    h_gemm<2><<<dim3(EMB / BN, BT / BM), 256, GEMM_SMEM>>>(
        pff, pw2, fc2b, px2, out, nullptr, BT, EMB, FF);
}